// round 1
// baseline (speedup 1.0000x reference)
#include <cuda_runtime.h>
#include <cstdint>

typedef unsigned long long ull;

#define NQ 6
#define DIMST 64
#define BMAX 32768

// ---------------- scratch (static device globals: no allocation) ----------------
__device__ float g_angles[BMAX * 6];
__device__ float g_gact[(size_t)BMAX * 128];
__device__ float g_rot[18 * 8];

// ---------------- f32x2 packed helpers ----------------
__device__ __forceinline__ ull f2pack(float a, float b) {
    ull r;
    asm("mov.b64 %0, {%1, %2};" : "=l"(r) : "r"(__float_as_uint(a)), "r"(__float_as_uint(b)));
    return r;
}
__device__ __forceinline__ void f2unpack(ull v, float& a, float& b) {
    unsigned int lo, hi;
    asm("mov.b64 {%0, %1}, %2;" : "=r"(lo), "=r"(hi) : "l"(v));
    a = __uint_as_float(lo); b = __uint_as_float(hi);
}
__device__ __forceinline__ ull ffma2(ull a, ull b, ull c) {
    ull d;
    asm("fma.rn.f32x2 %0, %1, %2, %3;" : "=l"(d) : "l"(a), "l"(b), "l"(c));
    return d;
}

// ---------------- K0: precompute Rot matrices (batch-invariant) ----------------
__global__ void k0_rot(const float* __restrict__ qw) {
    int t = threadIdx.x;
    if (t >= 18) return;
    float phi = qw[t * 3 + 0], th = qw[t * 3 + 1], om = qw[t * 3 + 2];
    float c = cosf(th * 0.5f), s = sinf(th * 0.5f);
    // ep = e^{-i(phi+om)/2} = (cp, sp) with ap = -(phi+om)/2
    float ap = -(phi + om) * 0.5f, am = -(phi - om) * 0.5f;
    float sp, cp, sm, cm;
    sincosf(ap, &sp, &cp);
    sincosf(am, &sm, &cm);
    // u00 = ep*c ; u01 = -conj(em)*s ; u10 = em*s ; u11 = conj(ep)*c
    float* r = g_rot + t * 8;
    r[0] = cp * c;  r[1] = sp * c;
    r[2] = -cm * s; r[3] = sm * s;
    r[4] = cm * s;  r[5] = sm * s;
    r[6] = cp * c;  r[7] = -sp * c;
}

// ---------------- K1: encoder  x[B,512] -> angles[B,6] ----------------
// thread-per-sample; enc_w1 (64KB) staged in dynamic smem; packed f32x2 FMA.
extern __shared__ float sw1[];  // 512*32 floats

__global__ void k1_encoder(const float* __restrict__ x,
                           const float* __restrict__ w1,
                           const float* __restrict__ b1,
                           const float* __restrict__ w2,
                           const float* __restrict__ b2, int B) {
    // cooperative stage of w1 into smem
    const float4* w1v = (const float4*)w1;
    float4* sv = (float4*)sw1;
    for (int i = threadIdx.x; i < (512 * 32) / 4; i += blockDim.x) sv[i] = w1v[i];
    __syncthreads();

    int s = blockIdx.x * blockDim.x + threadIdx.x;
    if (s >= B) return;

    const float4* xr = (const float4*)(x + (size_t)s * 512);
    ull acc[16];
#pragma unroll
    for (int p = 0; p < 16; p++) acc[p] = f2pack(b1[2 * p], b1[2 * p + 1]);

    for (int k4 = 0; k4 < 128; k4++) {
        float4 xv = xr[k4];
        float xs4[4] = {xv.x, xv.y, xv.z, xv.w};
#pragma unroll
        for (int u = 0; u < 4; u++) {
            ull xd = f2pack(xs4[u], xs4[u]);
            const ulonglong2* wr = (const ulonglong2*)(sw1 + (k4 * 4 + u) * 32);
#pragma unroll
            for (int p2 = 0; p2 < 8; p2++) {
                ulonglong2 wp = wr[p2];
                acc[2 * p2]     = ffma2(xd, wp.x, acc[2 * p2]);
                acc[2 * p2 + 1] = ffma2(xd, wp.y, acc[2 * p2 + 1]);
            }
        }
    }
    float h[32];
#pragma unroll
    for (int p = 0; p < 16; p++) {
        float a, b;
        f2unpack(acc[p], a, b);
        h[2 * p] = tanhf(a);
        h[2 * p + 1] = tanhf(b);
    }
#pragma unroll
    for (int i = 0; i < 6; i++) {
        float a = b2[i];
#pragma unroll
        for (int j = 0; j < 32; j++) a += h[j] * w2[j * 6 + i];
        g_angles[s * 6 + i] = a;
    }
}

// ---------------- K2: quantum circuit, warp-per-sample ----------------
__device__ __forceinline__ float2 shflx(float2 v, int m) {
    float2 r;
    r.x = __shfl_xor_sync(0xffffffffu, v.x, m);
    r.y = __shfl_xor_sync(0xffffffffu, v.y, m);
    return r;
}
__device__ __forceinline__ float2 cmul(float2 a, float2 b) {
    return make_float2(a.x * b.x - a.y * b.y, a.x * b.y + a.y * b.x);
}
__device__ __forceinline__ float2 cmadd(float2 a, float2 b, float2 acc) {
    // acc + a*b
    return make_float2(acc.x + a.x * b.x - a.y * b.y, acc.y + a.x * b.y + a.y * b.x);
}

// RY on index bit b (U=[[c,-s],[s,c]])
__device__ __forceinline__ void apply_ry(float2& A0, float2& A1, float c, float s,
                                         int b, int lane) {
    if (b == 0) {
        float2 n0 = make_float2(c * A0.x - s * A1.x, c * A0.y - s * A1.y);
        float2 n1 = make_float2(s * A0.x + c * A1.x, s * A0.y + c * A1.y);
        A0 = n0; A1 = n1;
    } else {
        int m = 1 << (b - 1);
        float sg = (lane & m) ? s : -s;
        float2 p0 = shflx(A0, m), p1 = shflx(A1, m);
        A0 = make_float2(c * A0.x + sg * p0.x, c * A0.y + sg * p0.y);
        A1 = make_float2(c * A1.x + sg * p1.x, c * A1.y + sg * p1.y);
    }
}
__device__ __forceinline__ void apply_rot(float2& A0, float2& A1, float2 u00, float2 u01,
                                          float2 u10, float2 u11, int b, int lane) {
    if (b == 0) {
        float2 n0 = cmadd(u01, A1, cmul(u00, A0));
        float2 n1 = cmadd(u11, A1, cmul(u10, A0));
        A0 = n0; A1 = n1;
    } else {
        int m = 1 << (b - 1);
        bool hi = (lane & m) != 0;
        float2 ua = hi ? u11 : u00;
        float2 ub = hi ? u10 : u01;
        float2 p0 = shflx(A0, m), p1 = shflx(A1, m);
        A0 = cmadd(ub, p0, cmul(ua, A0));
        A1 = cmadd(ub, p1, cmul(ua, A1));
    }
}

__global__ void k2_circuit(const float* __restrict__ hw1,
                           const float* __restrict__ hb1, int B) {
    int gt = blockIdx.x * blockDim.x + threadIdx.x;
    int s = gt >> 5, lane = gt & 31;
    if (s >= B) return;

    float cs[6], sn[6];
#pragma unroll
    for (int q = 0; q < 6; q++) {
        float a = g_angles[s * 6 + q];
        __sincosf(0.5f * a, &sn[q], &cs[q]);
    }

    // amp index a = lane*2 + r ; qubit q <-> index bit (5-q)
    float2 A0 = make_float2(lane == 0 ? 1.f : 0.f, 0.f);
    float2 A1 = make_float2(0.f, 0.f);

#pragma unroll
    for (int L = 0; L < 3; L++) {
        // data re-uploading RY
#pragma unroll
        for (int q = 0; q < 6; q++) apply_ry(A0, A1, cs[q], sn[q], 5 - q, lane);
        // trainable Rot
#pragma unroll
        for (int q = 0; q < 6; q++) {
            const float* u = g_rot + (L * 6 + q) * 8;
            float2 u00 = make_float2(u[0], u[1]);
            float2 u01 = make_float2(u[2], u[3]);
            float2 u10 = make_float2(u[4], u[5]);
            float2 u11 = make_float2(u[6], u[7]);
            apply_rot(A0, A1, u00, u01, u10, u11, 5 - q, lane);
        }
        // CNOT(0,1): ctrl bit5(lane b4), tgt bit4(lane b3)
        { float2 p0 = shflx(A0, 8), p1 = shflx(A1, 8);
          if (lane & 16) { A0 = p0; A1 = p1; } }
        // CNOT(2,3): ctrl bit3(lane b2), tgt bit2(lane b1)
        { float2 p0 = shflx(A0, 2), p1 = shflx(A1, 2);
          if (lane & 4) { A0 = p0; A1 = p1; } }
        // CNOT(4,5): ctrl bit1(lane b0), tgt bit0(local)
        { if (lane & 1) { float2 t = A0; A0 = A1; A1 = t; } }
        // CNOT(1,2): ctrl bit4(lane b3), tgt bit3(lane b2)
        { float2 p0 = shflx(A0, 4), p1 = shflx(A1, 4);
          if (lane & 8) { A0 = p0; A1 = p1; } }
        // CNOT(3,4): ctrl bit2(lane b1), tgt bit1(lane b0)
        { float2 p0 = shflx(A0, 1), p1 = shflx(A1, 1);
          if (lane & 2) { A0 = p0; A1 = p1; } }
        // CNOT(5,0): ctrl bit0(=r), tgt bit5(lane b4): all r=1 amps exchange
        { A1 = shflx(A1, 16); }
    }

    // expvals <Z_q>
    float p0 = A0.x * A0.x + A0.y * A0.y;
    float p1 = A1.x * A1.x + A1.y * A1.y;
    float z[6];
#pragma unroll
    for (int q = 0; q < 6; q++) {
        int b = 5 - q;
        if (b == 0) z[q] = p0 - p1;
        else {
            float sgn = ((lane >> (b - 1)) & 1) ? -1.f : 1.f;
            z[q] = sgn * (p0 + p1);
        }
    }
#pragma unroll
    for (int off = 16; off; off >>= 1) {
#pragma unroll
        for (int q = 0; q < 6; q++) z[q] += __shfl_xor_sync(0xffffffffu, z[q], off);
    }

    // head layer 1: g = relu(z @ hw1[6,128] + hb1)
#pragma unroll
    for (int m2 = 0; m2 < 4; m2++) {
        int j = m2 * 32 + lane;
        float a = hb1[j];
#pragma unroll
        for (int i = 0; i < 6; i++) a += z[i] * hw1[i * 128 + j];
        g_gact[(size_t)s * 128 + j] = fmaxf(a, 0.f);
    }
}

// ---------------- K3: logits = g[B,128] @ w2[128,1296] + b2 ----------------
// 128x128 block tile, 8x8 per thread, packed f32x2 FMA.
__global__ __launch_bounds__(256, 2)
void k3_gemm(const float* __restrict__ w2, const float* __restrict__ b2,
             float* __restrict__ out, int B) {
    __shared__ float sA[8][128];  // [k][m]
    __shared__ float sB[8][128];  // [k][n]

    const int N = 1296;
    int tid = threadIdx.x;
    int tx = tid & 15, ty = tid >> 4;
    int n0 = blockIdx.x * 128;
    int m0 = blockIdx.y * 128;

    int lm = tid >> 1, lh = tid & 1;          // A loader: row lm, float4 half lh
    int lk = tid >> 5, ln4 = (tid & 31) * 4;  // B loader: k row lk, col ln4

    ull acc[8][4];
#pragma unroll
    for (int i = 0; i < 8; i++)
#pragma unroll
        for (int j = 0; j < 4; j++) acc[i][j] = 0ULL;

    for (int kt = 0; kt < 16; kt++) {
        // global loads (before sync, into regs)
        float4 av = make_float4(0.f, 0.f, 0.f, 0.f);
        if (m0 + lm < B)
            av = *(const float4*)(g_gact + (size_t)(m0 + lm) * 128 + kt * 8 + lh * 4);
        float4 bv;
        {
            int col = n0 + ln4;
            const float* wrow = w2 + (size_t)(kt * 8 + lk) * N;
            if (col + 3 < N) {
                bv = *(const float4*)(wrow + col);
            } else {
                bv.x = (col + 0 < N) ? wrow[col + 0] : 0.f;
                bv.y = (col + 1 < N) ? wrow[col + 1] : 0.f;
                bv.z = (col + 2 < N) ? wrow[col + 2] : 0.f;
                bv.w = (col + 3 < N) ? wrow[col + 3] : 0.f;
            }
        }
        __syncthreads();  // previous compute done reading smem
        sA[lh * 4 + 0][lm] = av.x;
        sA[lh * 4 + 1][lm] = av.y;
        sA[lh * 4 + 2][lm] = av.z;
        sA[lh * 4 + 3][lm] = av.w;
        *(float4*)&sB[lk][ln4] = bv;
        __syncthreads();

#pragma unroll
        for (int k = 0; k < 8; k++) {
            float4 a0 = *(const float4*)&sA[k][ty * 8];
            float4 a1 = *(const float4*)&sA[k][ty * 8 + 4];
            ulonglong2 bb0 = *(const ulonglong2*)&sB[k][tx * 8];
            ulonglong2 bb1 = *(const ulonglong2*)&sB[k][tx * 8 + 4];
            ull bq[4] = {bb0.x, bb0.y, bb1.x, bb1.y};
            ull ad[8];
            ad[0] = f2pack(a0.x, a0.x); ad[1] = f2pack(a0.y, a0.y);
            ad[2] = f2pack(a0.z, a0.z); ad[3] = f2pack(a0.w, a0.w);
            ad[4] = f2pack(a1.x, a1.x); ad[5] = f2pack(a1.y, a1.y);
            ad[6] = f2pack(a1.z, a1.z); ad[7] = f2pack(a1.w, a1.w);
#pragma unroll
            for (int mi = 0; mi < 8; mi++)
#pragma unroll
                for (int np = 0; np < 4; np++)
                    acc[mi][np] = ffma2(ad[mi], bq[np], acc[mi][np]);
        }
    }

    // epilogue
    int c0 = n0 + tx * 8;
    float bias[8];
#pragma unroll
    for (int j = 0; j < 8; j++) bias[j] = (c0 + j < N) ? b2[c0 + j] : 0.f;

#pragma unroll
    for (int mi = 0; mi < 8; mi++) {
        int row = m0 + ty * 8 + mi;
        if (row >= B) continue;
        float v[8];
#pragma unroll
        for (int np = 0; np < 4; np++) {
            float a, b;
            f2unpack(acc[mi][np], a, b);
            v[2 * np] = a + bias[2 * np];
            v[2 * np + 1] = b + bias[2 * np + 1];
        }
        float* orow = out + (size_t)row * N + c0;
        if (c0 + 7 < N) {
            *(float4*)(orow)     = make_float4(v[0], v[1], v[2], v[3]);
            *(float4*)(orow + 4) = make_float4(v[4], v[5], v[6], v[7]);
        } else {
#pragma unroll
            for (int j = 0; j < 8; j++)
                if (c0 + j < N) orow[j] = v[j];
        }
    }
}

// ---------------- launch ----------------
extern "C" void kernel_launch(void* const* d_in, const int* in_sizes, int n_in,
                              void* d_out, int out_size) {
    const float* x   = (const float*)d_in[0];
    const float* ew1 = (const float*)d_in[1];
    const float* eb1 = (const float*)d_in[2];
    const float* ew2 = (const float*)d_in[3];
    const float* eb2 = (const float*)d_in[4];
    const float* qw  = (const float*)d_in[5];
    const float* hw1 = (const float*)d_in[6];
    const float* hb1 = (const float*)d_in[7];
    const float* hw2 = (const float*)d_in[8];
    const float* hb2 = (const float*)d_in[9];
    float* out = (float*)d_out;

    int B = in_sizes[0] / 512;

    cudaFuncSetAttribute(k1_encoder, cudaFuncAttributeMaxDynamicSharedMemorySize, 65536);

    k0_rot<<<1, 32>>>(qw);
    k1_encoder<<<(B + 127) / 128, 128, 65536>>>(x, ew1, eb1, ew2, eb2, B);
    k2_circuit<<<(B * 32 + 255) / 256, 256>>>(hw1, hb1, B);
    dim3 g3((1296 + 127) / 128, (B + 127) / 128);
    k3_gemm<<<g3, 256>>>(hw2, hb2, out, B);
}

// round 3
// speedup vs baseline: 1.8408x; 1.8408x over previous
#include <cuda_runtime.h>
#include <cuda_fp16.h>
#include <cstdint>

typedef unsigned long long ull;

#define BMAX 32768

// ---------------- scratch (static device globals: no allocation) ----------------
__device__ float g_angles[BMAX * 6];
__device__ float g_rot[18 * 8];
__device__ __align__(16) __half g_af[(size_t)BMAX * 128];  // A (activations) fp16
__device__ __align__(16) __half g_bh[1296 * 128];          // w2^T hi  [N,K] fp16
__device__ __align__(16) __half g_bl[1296 * 128];          // w2^T lo  [N,K] fp16

// ---------------- f32x2 packed helpers (K1) ----------------
__device__ __forceinline__ ull f2pack(float a, float b) {
    ull r;
    asm("mov.b64 %0, {%1, %2};" : "=l"(r) : "r"(__float_as_uint(a)), "r"(__float_as_uint(b)));
    return r;
}
__device__ __forceinline__ void f2unpack(ull v, float& a, float& b) {
    unsigned int lo, hi;
    asm("mov.b64 {%0, %1}, %2;" : "=r"(lo), "=r"(hi) : "l"(v));
    a = __uint_as_float(lo); b = __uint_as_float(hi);
}
__device__ __forceinline__ ull ffma2(ull a, ull b, ull c) {
    ull d;
    asm("fma.rn.f32x2 %0, %1, %2, %3;" : "=l"(d) : "l"(a), "l"(b), "l"(c));
    return d;
}

// ---------------- mma/ldmatrix helpers ----------------
__device__ __forceinline__ uint32_t smem_u32(const void* p) {
    uint32_t a;
    asm("{ .reg .u64 t; cvta.to.shared.u64 t, %1; cvt.u32.u64 %0, t; }" : "=r"(a) : "l"(p));
    return a;
}
__device__ __forceinline__ void ldsm4(uint32_t& r0, uint32_t& r1, uint32_t& r2, uint32_t& r3,
                                      uint32_t a) {
    asm volatile("ldmatrix.sync.aligned.m8n8.x4.shared.b16 {%0,%1,%2,%3}, [%4];"
                 : "=r"(r0), "=r"(r1), "=r"(r2), "=r"(r3) : "r"(a));
}
__device__ __forceinline__ void ldsm2(uint32_t& r0, uint32_t& r1, uint32_t a) {
    asm volatile("ldmatrix.sync.aligned.m8n8.x2.shared.b16 {%0,%1}, [%2];"
                 : "=r"(r0), "=r"(r1) : "r"(a));
}
__device__ __forceinline__ void mma16816(float* d, uint32_t a0, uint32_t a1, uint32_t a2,
                                         uint32_t a3, uint32_t b0, uint32_t b1) {
    asm volatile(
        "mma.sync.aligned.m16n8k16.row.col.f32.f16.f16.f32 "
        "{%0,%1,%2,%3}, {%4,%5,%6,%7}, {%8,%9}, {%0,%1,%2,%3};"
        : "+f"(d[0]), "+f"(d[1]), "+f"(d[2]), "+f"(d[3])
        : "r"(a0), "r"(a1), "r"(a2), "r"(a3), "r"(b0), "r"(b1));
}
// swizzled smem addr: rows of 128 fp16 (256B = 16 chunks of 16B), chunk ^= row&7
__device__ __forceinline__ uint32_t smaddr(uint32_t base, int row, int c) {
    return base + row * 256 + (((uint32_t)(c ^ (row & 7))) << 4);
}

// ---------------- K0: precompute Rot matrices (batch-invariant) ----------------
__global__ void k0_rot(const float* __restrict__ qw) {
    int t = threadIdx.x;
    if (t >= 18) return;
    float phi = qw[t * 3 + 0], th = qw[t * 3 + 1], om = qw[t * 3 + 2];
    float c = cosf(th * 0.5f), s = sinf(th * 0.5f);
    float ap = -(phi + om) * 0.5f, am = -(phi - om) * 0.5f;
    float sp, cp, sm, cm;
    sincosf(ap, &sp, &cp);
    sincosf(am, &sm, &cm);
    float* r = g_rot + t * 8;
    r[0] = cp * c;  r[1] = sp * c;
    r[2] = -cm * s; r[3] = sm * s;
    r[4] = cm * s;  r[5] = sm * s;
    r[6] = cp * c;  r[7] = -sp * c;
}

// ---------------- K0b: transpose+split head_w2 [128,1296] -> fp16 hi/lo [1296,128] ----
__global__ void k_w2split(const float* __restrict__ w2) {
    int i = blockIdx.x * blockDim.x + threadIdx.x;
    if (i >= 1296 * 128) return;
    int n = i >> 7, k = i & 127;
    float v = w2[k * 1296 + n];
    __half h = __float2half_rn(v);
    g_bh[i] = h;
    g_bl[i] = __float2half_rn(v - __half2float(h));
}

// ---------------- K1: encoder  x[B,512] -> angles[B,6] ----------------
extern __shared__ float sw1[];  // 512*32 floats

__global__ void k1_encoder(const float* __restrict__ x,
                           const float* __restrict__ w1,
                           const float* __restrict__ b1,
                           const float* __restrict__ w2,
                           const float* __restrict__ b2, int B) {
    const float4* w1v = (const float4*)w1;
    float4* sv = (float4*)sw1;
    for (int i = threadIdx.x; i < (512 * 32) / 4; i += blockDim.x) sv[i] = w1v[i];
    __syncthreads();

    int s = blockIdx.x * blockDim.x + threadIdx.x;
    if (s >= B) return;

    const float4* xr = (const float4*)(x + (size_t)s * 512);
    ull acc[16];
#pragma unroll
    for (int p = 0; p < 16; p++) acc[p] = f2pack(b1[2 * p], b1[2 * p + 1]);

    for (int k4 = 0; k4 < 128; k4++) {
        float4 xv = xr[k4];
        float xs4[4] = {xv.x, xv.y, xv.z, xv.w};
#pragma unroll
        for (int u = 0; u < 4; u++) {
            ull xd = f2pack(xs4[u], xs4[u]);
            const ulonglong2* wr = (const ulonglong2*)(sw1 + (k4 * 4 + u) * 32);
#pragma unroll
            for (int p2 = 0; p2 < 8; p2++) {
                ulonglong2 wp = wr[p2];
                acc[2 * p2]     = ffma2(xd, wp.x, acc[2 * p2]);
                acc[2 * p2 + 1] = ffma2(xd, wp.y, acc[2 * p2 + 1]);
            }
        }
    }
    float h[32];
#pragma unroll
    for (int p = 0; p < 16; p++) {
        float a, b;
        f2unpack(acc[p], a, b);
        h[2 * p] = tanhf(a);
        h[2 * p + 1] = tanhf(b);
    }
#pragma unroll
    for (int i = 0; i < 6; i++) {
        float a = b2[i];
#pragma unroll
        for (int j = 0; j < 32; j++) a += h[j] * w2[j * 6 + i];
        g_angles[s * 6 + i] = a;
    }
}

// ---------------- K2: quantum circuit, warp-per-sample ----------------
__device__ __forceinline__ float2 shflx(float2 v, int m) {
    float2 r;
    r.x = __shfl_xor_sync(0xffffffffu, v.x, m);
    r.y = __shfl_xor_sync(0xffffffffu, v.y, m);
    return r;
}
__device__ __forceinline__ float2 cmul(float2 a, float2 b) {
    return make_float2(a.x * b.x - a.y * b.y, a.x * b.y + a.y * b.x);
}
__device__ __forceinline__ float2 cmadd(float2 a, float2 b, float2 acc) {
    return make_float2(acc.x + a.x * b.x - a.y * b.y, acc.y + a.x * b.y + a.y * b.x);
}

__device__ __forceinline__ void apply_ry(float2& A0, float2& A1, float c, float s,
                                         int b, int lane) {
    if (b == 0) {
        float2 n0 = make_float2(c * A0.x - s * A1.x, c * A0.y - s * A1.y);
        float2 n1 = make_float2(s * A0.x + c * A1.x, s * A0.y + c * A1.y);
        A0 = n0; A1 = n1;
    } else {
        int m = 1 << (b - 1);
        float sg = (lane & m) ? s : -s;
        float2 p0 = shflx(A0, m), p1 = shflx(A1, m);
        A0 = make_float2(c * A0.x + sg * p0.x, c * A0.y + sg * p0.y);
        A1 = make_float2(c * A1.x + sg * p1.x, c * A1.y + sg * p1.y);
    }
}
__device__ __forceinline__ void apply_rot(float2& A0, float2& A1, float2 u00, float2 u01,
                                          float2 u10, float2 u11, int b, int lane) {
    if (b == 0) {
        float2 n0 = cmadd(u01, A1, cmul(u00, A0));
        float2 n1 = cmadd(u11, A1, cmul(u10, A0));
        A0 = n0; A1 = n1;
    } else {
        int m = 1 << (b - 1);
        bool hi = (lane & m) != 0;
        float2 ua = hi ? u11 : u00;
        float2 ub = hi ? u10 : u01;
        float2 p0 = shflx(A0, m), p1 = shflx(A1, m);
        A0 = cmadd(ub, p0, cmul(ua, A0));
        A1 = cmadd(ub, p1, cmul(ua, A1));
    }
}

__global__ void k2_circuit(const float* __restrict__ hw1,
                           const float* __restrict__ hb1, int B) {
    int gt = blockIdx.x * blockDim.x + threadIdx.x;
    int s = gt >> 5, lane = gt & 31;
    if (s >= B) return;

    float cs[6], sn[6];
#pragma unroll
    for (int q = 0; q < 6; q++) {
        float a = g_angles[s * 6 + q];
        __sincosf(0.5f * a, &sn[q], &cs[q]);
    }

    float2 A0 = make_float2(lane == 0 ? 1.f : 0.f, 0.f);
    float2 A1 = make_float2(0.f, 0.f);

#pragma unroll
    for (int L = 0; L < 3; L++) {
#pragma unroll
        for (int q = 0; q < 6; q++) apply_ry(A0, A1, cs[q], sn[q], 5 - q, lane);
#pragma unroll
        for (int q = 0; q < 6; q++) {
            const float* u = g_rot + (L * 6 + q) * 8;
            float2 u00 = make_float2(u[0], u[1]);
            float2 u01 = make_float2(u[2], u[3]);
            float2 u10 = make_float2(u[4], u[5]);
            float2 u11 = make_float2(u[6], u[7]);
            apply_rot(A0, A1, u00, u01, u10, u11, 5 - q, lane);
        }
        { float2 p0 = shflx(A0, 8), p1 = shflx(A1, 8);
          if (lane & 16) { A0 = p0; A1 = p1; } }
        { float2 p0 = shflx(A0, 2), p1 = shflx(A1, 2);
          if (lane & 4) { A0 = p0; A1 = p1; } }
        { if (lane & 1) { float2 t = A0; A0 = A1; A1 = t; } }
        { float2 p0 = shflx(A0, 4), p1 = shflx(A1, 4);
          if (lane & 8) { A0 = p0; A1 = p1; } }
        { float2 p0 = shflx(A0, 1), p1 = shflx(A1, 1);
          if (lane & 2) { A0 = p0; A1 = p1; } }
        { A1 = shflx(A1, 16); }
    }

    float p0 = A0.x * A0.x + A0.y * A0.y;
    float p1 = A1.x * A1.x + A1.y * A1.y;
    float z[6];
#pragma unroll
    for (int q = 0; q < 6; q++) {
        int b = 5 - q;
        if (b == 0) z[q] = p0 - p1;
        else {
            float sgn = ((lane >> (b - 1)) & 1) ? -1.f : 1.f;
            z[q] = sgn * (p0 + p1);
        }
    }
#pragma unroll
    for (int off = 16; off; off >>= 1) {
#pragma unroll
        for (int q = 0; q < 6; q++) z[q] += __shfl_xor_sync(0xffffffffu, z[q], off);
    }

    // head layer 1 -> fp16 A for tensor GEMM
#pragma unroll
    for (int m2 = 0; m2 < 4; m2++) {
        int j = m2 * 32 + lane;
        float a = hb1[j];
#pragma unroll
        for (int i = 0; i < 6; i++) a += z[i] * hw1[i * 128 + j];
        a = fmaxf(a, 0.f);
        g_af[(size_t)s * 128 + j] = __float2half_rn(a);
    }
}

// ---------------- K3: HMMA fp16 2-pass GEMM  out = A[B,128] @ w2[128,1296] + b2 ----
// CTA tile 128(M) x 72(N), K=128 in smem. warp w -> rows [16w,16w+16), 9 n-frags.
#define K3_SMEM (32768 + 18432 + 18432)

__global__ __launch_bounds__(256, 2)
void k3_mma(const float* __restrict__ b2, float* __restrict__ out, int B) {
    extern __shared__ char sm3[];
    __half* sA  = (__half*)sm3;                    // 128 x 128
    __half* sBh = (__half*)(sm3 + 32768);          // 72 x 128
    __half* sBl = (__half*)(sm3 + 32768 + 18432);  // 72 x 128

    int tid = threadIdx.x, lane = tid & 31, wid = tid >> 5;
    int n0 = blockIdx.x * 72;
    int m0 = blockIdx.y * 128;

    // stage A (swizzled 16B chunks)
    const uint4* gA = (const uint4*)g_af + (size_t)m0 * 16;
    uint4* dA = (uint4*)sA;
#pragma unroll
    for (int it = 0; it < 8; it++) {
        int i = it * 256 + tid;
        int r = i >> 4, c = i & 15;
        dA[r * 16 + (c ^ (r & 7))] = gA[i];
    }
    // stage Bh/Bl
    const uint4* gBh = (const uint4*)g_bh + (size_t)n0 * 16;
    const uint4* gBl = (const uint4*)g_bl + (size_t)n0 * 16;
    uint4* dBh = (uint4*)sBh;
    uint4* dBl = (uint4*)sBl;
    for (int i = tid; i < 72 * 16; i += 256) {
        int r = i >> 4, c = i & 15;
        int d = r * 16 + (c ^ (r & 7));
        dBh[d] = gBh[i];
        dBl[d] = gBl[i];
    }
    __syncthreads();

    uint32_t sAb = smem_u32(sA), sBhb = smem_u32(sBh), sBlb = smem_u32(sBl);
    int la = lane & 7, hb = (lane >> 3) & 1, hc = lane >> 4;
    int arow = wid * 16 + la + (hb << 3);
    int brow = la + (hb << 3);

    float acc[9][4];
#pragma unroll
    for (int j = 0; j < 9; j++)
#pragma unroll
        for (int v = 0; v < 4; v++) acc[j][v] = 0.f;

#pragma unroll
    for (int ks = 0; ks < 8; ks++) {
        int ca = 2 * ks + hc;
        uint32_t a0, a1, a2, a3;
        ldsm4(a0, a1, a2, a3, smaddr(sAb, arow, ca));

        // hi pass
#pragma unroll
        for (int p = 0; p < 4; p++) {
            uint32_t r0, r1, r2, r3;
            ldsm4(r0, r1, r2, r3, smaddr(sBhb, p * 16 + brow, ca));
            mma16816(acc[2 * p],     a0, a1, a2, a3, r0, r2);
            mma16816(acc[2 * p + 1], a0, a1, a2, a3, r1, r3);
        }
        {
            uint32_t r0, r1;
            ldsm2(r0, r1, smaddr(sBhb, 64 + la, 2 * ks + hb));
            mma16816(acc[8], a0, a1, a2, a3, r0, r1);
        }
        // lo pass
#pragma unroll
        for (int p = 0; p < 4; p++) {
            uint32_t r0, r1, r2, r3;
            ldsm4(r0, r1, r2, r3, smaddr(sBlb, p * 16 + brow, ca));
            mma16816(acc[2 * p],     a0, a1, a2, a3, r0, r2);
            mma16816(acc[2 * p + 1], a0, a1, a2, a3, r1, r3);
        }
        {
            uint32_t r0, r1;
            ldsm2(r0, r1, smaddr(sBlb, 64 + la, 2 * ks + hb));
            mma16816(acc[8], a0, a1, a2, a3, r0, r1);
        }
    }

    // epilogue: d0,d1 -> row lane>>2; d2,d3 -> row+8; cols 2*(lane&3)+{0,1} per frag
    int orow0 = m0 + wid * 16 + (lane >> 2);
    float* op = out + (size_t)orow0 * 1296 + n0 + 2 * (lane & 3);
    const float* bp = b2 + n0 + 2 * (lane & 3);
#pragma unroll
    for (int j = 0; j < 9; j++) {
        float2 bias = *(const float2*)(bp + 8 * j);
        float2 v0 = make_float2(acc[j][0] + bias.x, acc[j][1] + bias.y);
        float2 v1 = make_float2(acc[j][2] + bias.x, acc[j][3] + bias.y);
        *(float2*)(op + 8 * j) = v0;
        *(float2*)(op + 8 * j + 8 * 1296) = v1;
    }
}

// ---------------- launch ----------------
extern "C" void kernel_launch(void* const* d_in, const int* in_sizes, int n_in,
                              void* d_out, int out_size) {
    const float* x   = (const float*)d_in[0];
    const float* ew1 = (const float*)d_in[1];
    const float* eb1 = (const float*)d_in[2];
    const float* ew2 = (const float*)d_in[3];
    const float* eb2 = (const float*)d_in[4];
    const float* qw  = (const float*)d_in[5];
    const float* hw1 = (const float*)d_in[6];
    const float* hb1 = (const float*)d_in[7];
    const float* hw2 = (const float*)d_in[8];
    const float* hb2 = (const float*)d_in[9];
    float* out = (float*)d_out;

    int B = in_sizes[0] / 512;

    cudaFuncSetAttribute(k1_encoder, cudaFuncAttributeMaxDynamicSharedMemorySize, 65536);
    cudaFuncSetAttribute(k3_mma, cudaFuncAttributeMaxDynamicSharedMemorySize, K3_SMEM);

    k0_rot<<<1, 32>>>(qw);
    k_w2split<<<(1296 * 128 + 255) / 256, 256>>>(hw2);
    k1_encoder<<<(B + 127) / 128, 128, 65536>>>(x, ew1, eb1, ew2, eb2, B);
    k2_circuit<<<(B * 32 + 255) / 256, 256>>>(hw1, hb1, B);
    dim3 g3(18, B / 128);
    k3_mma<<<g3, 256, K3_SMEM>>>(hb2, out, B);
}

// round 4
// speedup vs baseline: 2.0612x; 1.1197x over previous
#include <cuda_runtime.h>
#include <cuda_fp16.h>
#include <cstdint>

typedef unsigned long long ull;

#define BMAX 32768

// ---------------- scratch (static device globals: no allocation) ----------------
__device__ float g_angles[BMAX * 6];
__device__ float g_rot[18 * 8];
__device__ __align__(16) __half g_af[(size_t)BMAX * 128];  // A (activations) fp16
__device__ __align__(16) __half g_bh[1296 * 128];          // w2^T fp16 [N,K]

// ---------------- f32x2 packed helpers (K1) ----------------
__device__ __forceinline__ ull f2pack(float a, float b) {
    ull r;
    asm("mov.b64 %0, {%1, %2};" : "=l"(r) : "r"(__float_as_uint(a)), "r"(__float_as_uint(b)));
    return r;
}
__device__ __forceinline__ void f2unpack(ull v, float& a, float& b) {
    unsigned int lo, hi;
    asm("mov.b64 {%0, %1}, %2;" : "=r"(lo), "=r"(hi) : "l"(v));
    a = __uint_as_float(lo); b = __uint_as_float(hi);
}
__device__ __forceinline__ ull ffma2(ull a, ull b, ull c) {
    ull d;
    asm("fma.rn.f32x2 %0, %1, %2, %3;" : "=l"(d) : "l"(a), "l"(b), "l"(c));
    return d;
}

// ---------------- mma/ldmatrix helpers ----------------
__device__ __forceinline__ uint32_t smem_u32(const void* p) {
    uint32_t a;
    asm("{ .reg .u64 t; cvta.to.shared.u64 t, %1; cvt.u32.u64 %0, t; }" : "=r"(a) : "l"(p));
    return a;
}
__device__ __forceinline__ void ldsm4(uint32_t& r0, uint32_t& r1, uint32_t& r2, uint32_t& r3,
                                      uint32_t a) {
    asm volatile("ldmatrix.sync.aligned.m8n8.x4.shared.b16 {%0,%1,%2,%3}, [%4];"
                 : "=r"(r0), "=r"(r1), "=r"(r2), "=r"(r3) : "r"(a));
}
__device__ __forceinline__ void ldsm2(uint32_t& r0, uint32_t& r1, uint32_t a) {
    asm volatile("ldmatrix.sync.aligned.m8n8.x2.shared.b16 {%0,%1}, [%2];"
                 : "=r"(r0), "=r"(r1) : "r"(a));
}
__device__ __forceinline__ void mma16816(float* d, uint32_t a0, uint32_t a1, uint32_t a2,
                                         uint32_t a3, uint32_t b0, uint32_t b1) {
    asm volatile(
        "mma.sync.aligned.m16n8k16.row.col.f32.f16.f16.f32 "
        "{%0,%1,%2,%3}, {%4,%5,%6,%7}, {%8,%9}, {%0,%1,%2,%3};"
        : "+f"(d[0]), "+f"(d[1]), "+f"(d[2]), "+f"(d[3])
        : "r"(a0), "r"(a1), "r"(a2), "r"(a3), "r"(b0), "r"(b1));
}
// swizzled smem addr: rows of 128 fp16 (256B = 16 chunks of 16B), chunk ^= row&7
__device__ __forceinline__ uint32_t smaddr(uint32_t base, int row, int c) {
    return base + row * 256 + (((uint32_t)(c ^ (row & 7))) << 4);
}

// ---------------- K0: precompute Rot matrices (batch-invariant) ----------------
__global__ void k0_rot(const float* __restrict__ qw) {
    int t = threadIdx.x;
    if (t >= 18) return;
    float phi = qw[t * 3 + 0], th = qw[t * 3 + 1], om = qw[t * 3 + 2];
    float c = cosf(th * 0.5f), s = sinf(th * 0.5f);
    float ap = -(phi + om) * 0.5f, am = -(phi - om) * 0.5f;
    float sp, cp, sm, cm;
    sincosf(ap, &sp, &cp);
    sincosf(am, &sm, &cm);
    float* r = g_rot + t * 8;
    r[0] = cp * c;  r[1] = sp * c;
    r[2] = -cm * s; r[3] = sm * s;
    r[4] = cm * s;  r[5] = sm * s;
    r[6] = cp * c;  r[7] = -sp * c;
}

// ---------------- K0b: transpose head_w2 [128,1296] -> fp16 [1296,128] ----------------
__global__ void k_w2split(const float* __restrict__ w2) {
    int i = blockIdx.x * blockDim.x + threadIdx.x;
    if (i >= 1296 * 128) return;
    int n = i >> 7, k = i & 127;
    g_bh[i] = __float2half_rn(w2[k * 1296 + n]);
}

// ---------------- K1: encoder  x[B,512] -> angles[B,6] ----------------
extern __shared__ float sw1[];  // 512*32 floats

__global__ void k1_encoder(const float* __restrict__ x,
                           const float* __restrict__ w1,
                           const float* __restrict__ b1,
                           const float* __restrict__ w2,
                           const float* __restrict__ b2, int B) {
    const float4* w1v = (const float4*)w1;
    float4* sv = (float4*)sw1;
    for (int i = threadIdx.x; i < (512 * 32) / 4; i += blockDim.x) sv[i] = w1v[i];
    __syncthreads();

    int s = blockIdx.x * blockDim.x + threadIdx.x;
    if (s >= B) return;

    const float4* xr = (const float4*)(x + (size_t)s * 512);
    ull acc[16];
#pragma unroll
    for (int p = 0; p < 16; p++) acc[p] = f2pack(b1[2 * p], b1[2 * p + 1]);

    for (int k4 = 0; k4 < 128; k4++) {
        float4 xv = xr[k4];
        float xs4[4] = {xv.x, xv.y, xv.z, xv.w};
#pragma unroll
        for (int u = 0; u < 4; u++) {
            ull xd = f2pack(xs4[u], xs4[u]);
            const ulonglong2* wr = (const ulonglong2*)(sw1 + (k4 * 4 + u) * 32);
#pragma unroll
            for (int p2 = 0; p2 < 8; p2++) {
                ulonglong2 wp = wr[p2];
                acc[2 * p2]     = ffma2(xd, wp.x, acc[2 * p2]);
                acc[2 * p2 + 1] = ffma2(xd, wp.y, acc[2 * p2 + 1]);
            }
        }
    }
    float h[32];
#pragma unroll
    for (int p = 0; p < 16; p++) {
        float a, b;
        f2unpack(acc[p], a, b);
        h[2 * p] = tanhf(a);
        h[2 * p + 1] = tanhf(b);
    }
#pragma unroll
    for (int i = 0; i < 6; i++) {
        float a = b2[i];
#pragma unroll
        for (int j = 0; j < 32; j++) a += h[j] * w2[j * 6 + i];
        g_angles[s * 6 + i] = a;
    }
}

// ---------------- K2: quantum circuit, warp-per-sample, fused RY+Rot gates ----------------
__device__ __forceinline__ float2 shflx(float2 v, int m) {
    float2 r;
    r.x = __shfl_xor_sync(0xffffffffu, v.x, m);
    r.y = __shfl_xor_sync(0xffffffffu, v.y, m);
    return r;
}
__device__ __forceinline__ float2 cmul(float2 a, float2 b) {
    return make_float2(a.x * b.x - a.y * b.y, a.x * b.y + a.y * b.x);
}
__device__ __forceinline__ float2 cmadd(float2 a, float2 b, float2 acc) {
    return make_float2(acc.x + a.x * b.x - a.y * b.y, acc.y + a.x * b.y + a.y * b.x);
}

// general 2x2 complex gate on index bit b
__device__ __forceinline__ void apply_g(float2& A0, float2& A1, float2 u00, float2 u01,
                                        float2 u10, float2 u11, int b, int lane) {
    if (b == 0) {
        float2 n0 = cmadd(u01, A1, cmul(u00, A0));
        float2 n1 = cmadd(u11, A1, cmul(u10, A0));
        A0 = n0; A1 = n1;
    } else {
        int m = 1 << (b - 1);
        bool hi = (lane & m) != 0;
        float2 ua = hi ? u11 : u00;
        float2 ub = hi ? u10 : u01;
        float2 p0 = shflx(A0, m), p1 = shflx(A1, m);
        A0 = cmadd(ub, p0, cmul(ua, A0));
        A1 = cmadd(ub, p1, cmul(ua, A1));
    }
}

__global__ void k2_circuit(const float* __restrict__ hw1,
                           const float* __restrict__ hb1, int B) {
    int gt = blockIdx.x * blockDim.x + threadIdx.x;
    int s = gt >> 5, lane = gt & 31;
    if (s >= B) return;

    float cs[6], sn[6];
#pragma unroll
    for (int q = 0; q < 6; q++) {
        float a = g_angles[s * 6 + q];
        __sincosf(0.5f * a, &sn[q], &cs[q]);
    }

    float2 A0 = make_float2(lane == 0 ? 1.f : 0.f, 0.f);
    float2 A1 = make_float2(0.f, 0.f);

#pragma unroll
    for (int L = 0; L < 3; L++) {
        // fused gate G_q = Rot_q * RY(a_q): gates on distinct qubits commute,
        // so (prod Rot)(prod RY) == prod_q (Rot_q RY_q).
#pragma unroll
        for (int q = 0; q < 6; q++) {
            const float* u = g_rot + (L * 6 + q) * 8;
            float c = cs[q], s2 = sn[q];
            float2 f00 = make_float2(u[0] * c + u[2] * s2, u[1] * c + u[3] * s2);
            float2 f01 = make_float2(u[2] * c - u[0] * s2, u[3] * c - u[1] * s2);
            float2 f10 = make_float2(u[4] * c + u[6] * s2, u[5] * c + u[7] * s2);
            float2 f11 = make_float2(u[6] * c - u[4] * s2, u[7] * c - u[5] * s2);
            apply_g(A0, A1, f00, f01, f10, f11, 5 - q, lane);
        }
        // CNOT ladder
        { float2 p0 = shflx(A0, 8), p1 = shflx(A1, 8);
          if (lane & 16) { A0 = p0; A1 = p1; } }
        { float2 p0 = shflx(A0, 2), p1 = shflx(A1, 2);
          if (lane & 4) { A0 = p0; A1 = p1; } }
        { if (lane & 1) { float2 t = A0; A0 = A1; A1 = t; } }
        { float2 p0 = shflx(A0, 4), p1 = shflx(A1, 4);
          if (lane & 8) { A0 = p0; A1 = p1; } }
        { float2 p0 = shflx(A0, 1), p1 = shflx(A1, 1);
          if (lane & 2) { A0 = p0; A1 = p1; } }
        { A1 = shflx(A1, 16); }
    }

    float p0 = A0.x * A0.x + A0.y * A0.y;
    float p1 = A1.x * A1.x + A1.y * A1.y;
    float z[6];
#pragma unroll
    for (int q = 0; q < 6; q++) {
        int b = 5 - q;
        if (b == 0) z[q] = p0 - p1;
        else {
            float sgn = ((lane >> (b - 1)) & 1) ? -1.f : 1.f;
            z[q] = sgn * (p0 + p1);
        }
    }
#pragma unroll
    for (int off = 16; off; off >>= 1) {
#pragma unroll
        for (int q = 0; q < 6; q++) z[q] += __shfl_xor_sync(0xffffffffu, z[q], off);
    }

    // head layer 1 -> fp16 A for tensor GEMM
#pragma unroll
    for (int m2 = 0; m2 < 4; m2++) {
        int j = m2 * 32 + lane;
        float a = hb1[j];
#pragma unroll
        for (int i = 0; i < 6; i++) a += z[i] * hw1[i * 128 + j];
        a = fmaxf(a, 0.f);
        g_af[(size_t)s * 128 + j] = __float2half_rn(a);
    }
}

// ---------------- K3: HMMA fp16 GEMM  out = A[B,128] @ w2[128,1296] + b2 ----
// CTA tile 128(M) x 72(N), K=128 in smem. warp w -> rows [16w,16w+16), 9 n-frags.
#define K3_SMEM (32768 + 18432)

__global__ __launch_bounds__(256, 2)
void k3_mma(const float* __restrict__ b2, float* __restrict__ out, int B) {
    extern __shared__ char sm3[];
    __half* sA  = (__half*)sm3;            // 128 x 128
    __half* sBh = (__half*)(sm3 + 32768);  // 72 x 128

    int tid = threadIdx.x, lane = tid & 31, wid = tid >> 5;
    int n0 = blockIdx.x * 72;
    int m0 = blockIdx.y * 128;

    // stage A (swizzled 16B chunks)
    const uint4* gA = (const uint4*)g_af + (size_t)m0 * 16;
    uint4* dA = (uint4*)sA;
#pragma unroll
    for (int it = 0; it < 8; it++) {
        int i = it * 256 + tid;
        int r = i >> 4, c = i & 15;
        dA[r * 16 + (c ^ (r & 7))] = gA[i];
    }
    // stage Bh
    const uint4* gBh = (const uint4*)g_bh + (size_t)n0 * 16;
    uint4* dBh = (uint4*)sBh;
    for (int i = tid; i < 72 * 16; i += 256) {
        int r = i >> 4, c = i & 15;
        dBh[r * 16 + (c ^ (r & 7))] = gBh[i];
    }
    __syncthreads();

    uint32_t sAb = smem_u32(sA), sBhb = smem_u32(sBh);
    int la = lane & 7, hb = (lane >> 3) & 1, hc = lane >> 4;
    int arow = wid * 16 + la + (hb << 3);
    int brow = la + (hb << 3);

    float acc[9][4];
#pragma unroll
    for (int j = 0; j < 9; j++)
#pragma unroll
        for (int v = 0; v < 4; v++) acc[j][v] = 0.f;

#pragma unroll
    for (int ks = 0; ks < 8; ks++) {
        int ca = 2 * ks + hc;
        uint32_t a0, a1, a2, a3;
        ldsm4(a0, a1, a2, a3, smaddr(sAb, arow, ca));

#pragma unroll
        for (int p = 0; p < 4; p++) {
            uint32_t r0, r1, r2, r3;
            ldsm4(r0, r1, r2, r3, smaddr(sBhb, p * 16 + brow, ca));
            mma16816(acc[2 * p],     a0, a1, a2, a3, r0, r2);
            mma16816(acc[2 * p + 1], a0, a1, a2, a3, r1, r3);
        }
        {
            uint32_t r0, r1;
            ldsm2(r0, r1, smaddr(sBhb, 64 + la, 2 * ks + hb));
            mma16816(acc[8], a0, a1, a2, a3, r0, r1);
        }
    }

    // epilogue: d0,d1 -> row lane>>2; d2,d3 -> row+8; cols 2*(lane&3)+{0,1} per frag
    int orow0 = m0 + wid * 16 + (lane >> 2);
    float* op = out + (size_t)orow0 * 1296 + n0 + 2 * (lane & 3);
    const float* bp = b2 + n0 + 2 * (lane & 3);
#pragma unroll
    for (int j = 0; j < 9; j++) {
        float2 bias = *(const float2*)(bp + 8 * j);
        float2 v0 = make_float2(acc[j][0] + bias.x, acc[j][1] + bias.y);
        float2 v1 = make_float2(acc[j][2] + bias.x, acc[j][3] + bias.y);
        *(float2*)(op + 8 * j) = v0;
        *(float2*)(op + 8 * j + 8 * 1296) = v1;
    }
}

// ---------------- launch ----------------
extern "C" void kernel_launch(void* const* d_in, const int* in_sizes, int n_in,
                              void* d_out, int out_size) {
    const float* x   = (const float*)d_in[0];
    const float* ew1 = (const float*)d_in[1];
    const float* eb1 = (const float*)d_in[2];
    const float* ew2 = (const float*)d_in[3];
    const float* eb2 = (const float*)d_in[4];
    const float* qw  = (const float*)d_in[5];
    const float* hw1 = (const float*)d_in[6];
    const float* hb1 = (const float*)d_in[7];
    const float* hw2 = (const float*)d_in[8];
    const float* hb2 = (const float*)d_in[9];
    float* out = (float*)d_out;

    int B = in_sizes[0] / 512;

    cudaFuncSetAttribute(k1_encoder, cudaFuncAttributeMaxDynamicSharedMemorySize, 65536);
    cudaFuncSetAttribute(k3_mma, cudaFuncAttributeMaxDynamicSharedMemorySize, K3_SMEM);

    k0_rot<<<1, 32>>>(qw);
    k_w2split<<<(1296 * 128 + 255) / 256, 256>>>(hw2);
    k1_encoder<<<(B + 127) / 128, 128, 65536>>>(x, ew1, eb1, ew2, eb2, B);
    k2_circuit<<<(B * 32 + 255) / 256, 256>>>(hw1, hb1, B);
    dim3 g3(18, B / 128);
    k3_mma<<<g3, 256, K3_SMEM>>>(hb2, out, B);
}

// round 5
// speedup vs baseline: 2.2751x; 1.1038x over previous
#include <cuda_runtime.h>
#include <cuda_fp16.h>
#include <cstdint>

typedef unsigned long long ull;

#define BMAX 32768

// ---------------- scratch (static device globals: no allocation) ----------------
__device__ float g_angles[BMAX * 6];
__device__ __align__(16) float g_rot[18 * 8];
__device__ __align__(16) __half g_af[(size_t)BMAX * 128];  // A (activations) fp16
__device__ __align__(16) __half g_bh[1296 * 128];          // w2^T fp16 [N,K]

// ---------------- f32x2 packed helpers ----------------
__device__ __forceinline__ ull f2pack(float a, float b) {
    ull r;
    asm("mov.b64 %0, {%1, %2};" : "=l"(r) : "r"(__float_as_uint(a)), "r"(__float_as_uint(b)));
    return r;
}
__device__ __forceinline__ void f2unpack(ull v, float& a, float& b) {
    unsigned int lo, hi;
    asm("mov.b64 {%0, %1}, %2;" : "=r"(lo), "=r"(hi) : "l"(v));
    a = __uint_as_float(lo); b = __uint_as_float(hi);
}
__device__ __forceinline__ ull ffma2(ull a, ull b, ull c) {
    ull d;
    asm("fma.rn.f32x2 %0, %1, %2, %3;" : "=l"(d) : "l"(a), "l"(b), "l"(c));
    return d;
}
__device__ __forceinline__ ull fmul2(ull a, ull b) {
    ull d;
    asm("mul.rn.f32x2 %0, %1, %2;" : "=l"(d) : "l"(a), "l"(b));
    return d;
}

// ---------------- mma/ldmatrix helpers ----------------
__device__ __forceinline__ uint32_t smem_u32(const void* p) {
    uint32_t a;
    asm("{ .reg .u64 t; cvta.to.shared.u64 t, %1; cvt.u32.u64 %0, t; }" : "=r"(a) : "l"(p));
    return a;
}
__device__ __forceinline__ void ldsm4(uint32_t& r0, uint32_t& r1, uint32_t& r2, uint32_t& r3,
                                      uint32_t a) {
    asm volatile("ldmatrix.sync.aligned.m8n8.x4.shared.b16 {%0,%1,%2,%3}, [%4];"
                 : "=r"(r0), "=r"(r1), "=r"(r2), "=r"(r3) : "r"(a));
}
__device__ __forceinline__ void mma16816(float* d, uint32_t a0, uint32_t a1, uint32_t a2,
                                         uint32_t a3, uint32_t b0, uint32_t b1) {
    asm volatile(
        "mma.sync.aligned.m16n8k16.row.col.f32.f16.f16.f32 "
        "{%0,%1,%2,%3}, {%4,%5,%6,%7}, {%8,%9}, {%0,%1,%2,%3};"
        : "+f"(d[0]), "+f"(d[1]), "+f"(d[2]), "+f"(d[3])
        : "r"(a0), "r"(a1), "r"(a2), "r"(a3), "r"(b0), "r"(b1));
}
// swizzled smem addr: rows of 128 fp16 (256B = 16 chunks of 16B), chunk ^= row&7
__device__ __forceinline__ uint32_t smaddr(uint32_t base, int row, int c) {
    return base + row * 256 + (((uint32_t)(c ^ (row & 7))) << 4);
}

// ---------------- K0: precompute Rot matrices (batch-invariant) ----------------
__global__ void k0_rot(const float* __restrict__ qw) {
    int t = threadIdx.x;
    if (t >= 18) return;
    float phi = qw[t * 3 + 0], th = qw[t * 3 + 1], om = qw[t * 3 + 2];
    float c = cosf(th * 0.5f), s = sinf(th * 0.5f);
    float ap = -(phi + om) * 0.5f, am = -(phi - om) * 0.5f;
    float sp, cp, sm, cm;
    sincosf(ap, &sp, &cp);
    sincosf(am, &sm, &cm);
    float* r = g_rot + t * 8;
    r[0] = cp * c;  r[1] = sp * c;
    r[2] = -cm * s; r[3] = sm * s;
    r[4] = cm * s;  r[5] = sm * s;
    r[6] = cp * c;  r[7] = -sp * c;
}

// ---------------- K0b: transpose head_w2 [128,1296] -> fp16 [1296,128] ----------------
__global__ void k_w2split(const float* __restrict__ w2) {
    int i = blockIdx.x * blockDim.x + threadIdx.x;
    if (i >= 1296 * 128) return;
    int n = i >> 7, k = i & 127;
    g_bh[i] = __float2half_rn(w2[k * 1296 + n]);
}

// ---------------- K1: encoder  x[B,512] -> angles[B,6] ----------------
extern __shared__ float sw1[];  // 512*32 floats

__global__ void k1_encoder(const float* __restrict__ x,
                           const float* __restrict__ w1,
                           const float* __restrict__ b1,
                           const float* __restrict__ w2,
                           const float* __restrict__ b2, int B) {
    const float4* w1v = (const float4*)w1;
    float4* sv = (float4*)sw1;
    for (int i = threadIdx.x; i < (512 * 32) / 4; i += blockDim.x) sv[i] = w1v[i];
    __syncthreads();

    int s = blockIdx.x * blockDim.x + threadIdx.x;
    if (s >= B) return;

    const float4* xr = (const float4*)(x + (size_t)s * 512);
    ull acc[16];
#pragma unroll
    for (int p = 0; p < 16; p++) acc[p] = f2pack(b1[2 * p], b1[2 * p + 1]);

    for (int k4 = 0; k4 < 128; k4++) {
        float4 xv = xr[k4];
        float xs4[4] = {xv.x, xv.y, xv.z, xv.w};
#pragma unroll
        for (int u = 0; u < 4; u++) {
            ull xd = f2pack(xs4[u], xs4[u]);
            const ulonglong2* wr = (const ulonglong2*)(sw1 + (k4 * 4 + u) * 32);
#pragma unroll
            for (int p2 = 0; p2 < 8; p2++) {
                ulonglong2 wp = wr[p2];
                acc[2 * p2]     = ffma2(xd, wp.x, acc[2 * p2]);
                acc[2 * p2 + 1] = ffma2(xd, wp.y, acc[2 * p2 + 1]);
            }
        }
    }
    float h[32];
#pragma unroll
    for (int p = 0; p < 16; p++) {
        float a, b;
        f2unpack(acc[p], a, b);
        h[2 * p] = tanhf(a);
        h[2 * p + 1] = tanhf(b);
    }
#pragma unroll
    for (int i = 0; i < 6; i++) {
        float a = b2[i];
#pragma unroll
        for (int j = 0; j < 32; j++) a += h[j] * w2[j * 6 + i];
        g_angles[s * 6 + i] = a;
    }
}

// ---------------- K2: quantum circuit, warp-per-sample, fused RY+Rot gates ----------------
__device__ __forceinline__ float2 shflx(float2 v, int m) {
    float2 r;
    r.x = __shfl_xor_sync(0xffffffffu, v.x, m);
    r.y = __shfl_xor_sync(0xffffffffu, v.y, m);
    return r;
}
__device__ __forceinline__ float2 cmul(float2 a, float2 b) {
    return make_float2(a.x * b.x - a.y * b.y, a.x * b.y + a.y * b.x);
}
__device__ __forceinline__ float2 cmadd(float2 a, float2 b, float2 acc) {
    return make_float2(acc.x + a.x * b.x - a.y * b.y, acc.y + a.x * b.y + a.y * b.x);
}

// general 2x2 complex gate on index bit b
__device__ __forceinline__ void apply_g(float2& A0, float2& A1, float2 u00, float2 u01,
                                        float2 u10, float2 u11, int b, int lane) {
    if (b == 0) {
        float2 n0 = cmadd(u01, A1, cmul(u00, A0));
        float2 n1 = cmadd(u11, A1, cmul(u10, A0));
        A0 = n0; A1 = n1;
    } else {
        int m = 1 << (b - 1);
        bool hi = (lane & m) != 0;
        float2 ua = hi ? u11 : u00;
        float2 ub = hi ? u10 : u01;
        float2 p0 = shflx(A0, m), p1 = shflx(A1, m);
        A0 = cmadd(ub, p0, cmul(ua, A0));
        A1 = cmadd(ub, p1, cmul(ua, A1));
    }
}

__global__ void k2_circuit(const float* __restrict__ hw1,
                           const float* __restrict__ hb1, int B) {
    int gt = blockIdx.x * blockDim.x + threadIdx.x;
    int s = gt >> 5, lane = gt & 31;
    if (s >= B) return;

    float cs[6], sn[6];
#pragma unroll
    for (int q = 0; q < 6; q++) {
        float a = g_angles[s * 6 + q];
        __sincosf(0.5f * a, &sn[q], &cs[q]);
    }

    float2 A0 = make_float2(lane == 0 ? 1.f : 0.f, 0.f);
    float2 A1 = make_float2(0.f, 0.f);

#pragma unroll
    for (int L = 0; L < 3; L++) {
        // fused gate G_q = Rot_q * RY(a_q), built with packed f32x2:
        // f00 = u01*c + u23*s ; f01 = u23*c - u01*s ; f10 = u45*c + u67*s ; f11 = u67*c - u45*s
#pragma unroll
        for (int q = 0; q < 6; q++) {
            const ull* up = (const ull*)(g_rot + (L * 6 + q) * 8);
            ull u01 = up[0], u23 = up[1], u45 = up[2], u67 = up[3];
            float c = cs[q], s2 = sn[q];
            ull cp = f2pack(c, c), sp = f2pack(s2, s2), sn2 = f2pack(-s2, -s2);
            ull f00p = ffma2(u23, sp, fmul2(u01, cp));
            ull f01p = ffma2(u01, sn2, fmul2(u23, cp));
            ull f10p = ffma2(u67, sp, fmul2(u45, cp));
            ull f11p = ffma2(u45, sn2, fmul2(u67, cp));
            float2 f00, f01, f10, f11;
            f2unpack(f00p, f00.x, f00.y);
            f2unpack(f01p, f01.x, f01.y);
            f2unpack(f10p, f10.x, f10.y);
            f2unpack(f11p, f11.x, f11.y);
            apply_g(A0, A1, f00, f01, f10, f11, 5 - q, lane);
        }
        // CNOT ladder
        { float2 p0 = shflx(A0, 8), p1 = shflx(A1, 8);
          if (lane & 16) { A0 = p0; A1 = p1; } }
        { float2 p0 = shflx(A0, 2), p1 = shflx(A1, 2);
          if (lane & 4) { A0 = p0; A1 = p1; } }
        { if (lane & 1) { float2 t = A0; A0 = A1; A1 = t; } }
        { float2 p0 = shflx(A0, 4), p1 = shflx(A1, 4);
          if (lane & 8) { A0 = p0; A1 = p1; } }
        { float2 p0 = shflx(A0, 1), p1 = shflx(A1, 1);
          if (lane & 2) { A0 = p0; A1 = p1; } }
        { A1 = shflx(A1, 16); }
    }

    float p0 = A0.x * A0.x + A0.y * A0.y;
    float p1 = A1.x * A1.x + A1.y * A1.y;
    float z[6];
#pragma unroll
    for (int q = 0; q < 6; q++) {
        int b = 5 - q;
        if (b == 0) z[q] = p0 - p1;
        else {
            float sgn = ((lane >> (b - 1)) & 1) ? -1.f : 1.f;
            z[q] = sgn * (p0 + p1);
        }
    }
#pragma unroll
    for (int off = 16; off; off >>= 1) {
#pragma unroll
        for (int q = 0; q < 6; q++) z[q] += __shfl_xor_sync(0xffffffffu, z[q], off);
    }

    // head layer 1 -> fp16 A for tensor GEMM
#pragma unroll
    for (int m2 = 0; m2 < 4; m2++) {
        int j = m2 * 32 + lane;
        float a = hb1[j];
#pragma unroll
        for (int i = 0; i < 6; i++) a += z[i] * hw1[i * 128 + j];
        a = fmaxf(a, 0.f);
        g_af[(size_t)s * 128 + j] = __float2half_rn(a);
    }
}

// ---------------- K3: HMMA fp16 GEMM  out = A[B,128] @ w2[128,1296] + b2 ----
// CTA tile 128(M) x 144(N), K=128 in smem. warp w -> rows [16w,16w+16), 18 n-frags.
#define K3_SMEM (32768 + 36864)

__global__ __launch_bounds__(256, 2)
void k3_mma(const float* __restrict__ b2, float* __restrict__ out, int B) {
    extern __shared__ char sm3[];
    __half* sA  = (__half*)sm3;            // 128 x 128
    __half* sBh = (__half*)(sm3 + 32768);  // 144 x 128

    int tid = threadIdx.x, lane = tid & 31, wid = tid >> 5;
    int n0 = blockIdx.x * 144;
    int m0 = blockIdx.y * 128;

    // stage A (swizzled 16B chunks)
    const uint4* gA = (const uint4*)g_af + (size_t)m0 * 16;
    uint4* dA = (uint4*)sA;
#pragma unroll
    for (int it = 0; it < 8; it++) {
        int i = it * 256 + tid;
        int r = i >> 4, c = i & 15;
        dA[r * 16 + (c ^ (r & 7))] = gA[i];
    }
    // stage B (144 rows x 16 chunks = 2304)
    const uint4* gBh = (const uint4*)g_bh + (size_t)n0 * 16;
    uint4* dBh = (uint4*)sBh;
#pragma unroll
    for (int it = 0; it < 9; it++) {
        int i = it * 256 + tid;
        int r = i >> 4, c = i & 15;
        dBh[r * 16 + (c ^ (r & 7))] = gBh[i];
    }
    __syncthreads();

    uint32_t sAb = smem_u32(sA), sBhb = smem_u32(sBh);
    int la = lane & 7, hb = (lane >> 3) & 1, hc = lane >> 4;
    int arow = wid * 16 + la + (hb << 3);
    int brow = la + (hb << 3);

    float acc[18][4];
#pragma unroll
    for (int j = 0; j < 18; j++)
#pragma unroll
        for (int v = 0; v < 4; v++) acc[j][v] = 0.f;

#pragma unroll
    for (int ks = 0; ks < 8; ks++) {
        int ca = 2 * ks + hc;
        uint32_t a0, a1, a2, a3;
        ldsm4(a0, a1, a2, a3, smaddr(sAb, arow, ca));

#pragma unroll
        for (int p = 0; p < 9; p++) {
            uint32_t r0, r1, r2, r3;
            ldsm4(r0, r1, r2, r3, smaddr(sBhb, p * 16 + brow, ca));
            mma16816(acc[2 * p],     a0, a1, a2, a3, r0, r2);
            mma16816(acc[2 * p + 1], a0, a1, a2, a3, r1, r3);
        }
    }

    // epilogue: d0,d1 -> row lane>>2; d2,d3 -> row+8; cols 2*(lane&3)+{0,1} per frag
    int orow0 = m0 + wid * 16 + (lane >> 2);
    float* op = out + (size_t)orow0 * 1296 + n0 + 2 * (lane & 3);
    const float* bp = b2 + n0 + 2 * (lane & 3);
#pragma unroll
    for (int j = 0; j < 18; j++) {
        float2 bias = *(const float2*)(bp + 8 * j);
        float2 v0 = make_float2(acc[j][0] + bias.x, acc[j][1] + bias.y);
        float2 v1 = make_float2(acc[j][2] + bias.x, acc[j][3] + bias.y);
        *(float2*)(op + 8 * j) = v0;
        *(float2*)(op + 8 * j + 8 * 1296) = v1;
    }
}

// ---------------- launch ----------------
extern "C" void kernel_launch(void* const* d_in, const int* in_sizes, int n_in,
                              void* d_out, int out_size) {
    const float* x   = (const float*)d_in[0];
    const float* ew1 = (const float*)d_in[1];
    const float* eb1 = (const float*)d_in[2];
    const float* ew2 = (const float*)d_in[3];
    const float* eb2 = (const float*)d_in[4];
    const float* qw  = (const float*)d_in[5];
    const float* hw1 = (const float*)d_in[6];
    const float* hb1 = (const float*)d_in[7];
    const float* hw2 = (const float*)d_in[8];
    const float* hb2 = (const float*)d_in[9];
    float* out = (float*)d_out;

    int B = in_sizes[0] / 512;

    cudaFuncSetAttribute(k1_encoder, cudaFuncAttributeMaxDynamicSharedMemorySize, 65536);
    cudaFuncSetAttribute(k3_mma, cudaFuncAttributeMaxDynamicSharedMemorySize, K3_SMEM);

    k0_rot<<<1, 32>>>(qw);
    k_w2split<<<(1296 * 128 + 255) / 256, 256>>>(hw2);
    k1_encoder<<<(B + 127) / 128, 128, 65536>>>(x, ew1, eb1, ew2, eb2, B);
    k2_circuit<<<(B * 32 + 255) / 256, 256>>>(hw1, hb1, B);
    dim3 g3(9, B / 128);
    k3_mma<<<g3, 256, K3_SMEM>>>(hb2, out, B);
}

// round 6
// speedup vs baseline: 2.4166x; 1.0622x over previous
#include <cuda_runtime.h>
#include <cuda_fp16.h>
#include <cstdint>

typedef unsigned long long ull;

#define BMAX 32768

// ---------------- scratch (static device globals: no allocation) ----------------
__device__ float g_angles[BMAX * 6];
__device__ __align__(16) float g_rot[18 * 8];
__device__ __align__(16) __half g_af[(size_t)BMAX * 128];  // A (activations) fp16
__device__ __align__(16) __half g_bh[1296 * 128];          // w2^T fp16 [N,K]

// ---------------- f32x2 packed helpers ----------------
__device__ __forceinline__ ull f2pack(float a, float b) {
    ull r;
    asm("mov.b64 %0, {%1, %2};" : "=l"(r) : "r"(__float_as_uint(a)), "r"(__float_as_uint(b)));
    return r;
}
__device__ __forceinline__ void f2unpack(ull v, float& a, float& b) {
    unsigned int lo, hi;
    asm("mov.b64 {%0, %1}, %2;" : "=r"(lo), "=r"(hi) : "l"(v));
    a = __uint_as_float(lo); b = __uint_as_float(hi);
}
__device__ __forceinline__ ull ffma2(ull a, ull b, ull c) {
    ull d;
    asm("fma.rn.f32x2 %0, %1, %2, %3;" : "=l"(d) : "l"(a), "l"(b), "l"(c));
    return d;
}
__device__ __forceinline__ ull fmul2(ull a, ull b) {
    ull d;
    asm("mul.rn.f32x2 %0, %1, %2;" : "=l"(d) : "l"(a), "l"(b));
    return d;
}

// ---------------- mma/ldmatrix helpers ----------------
__device__ __forceinline__ uint32_t smem_u32(const void* p) {
    uint32_t a;
    asm("{ .reg .u64 t; cvta.to.shared.u64 t, %1; cvt.u32.u64 %0, t; }" : "=r"(a) : "l"(p));
    return a;
}
__device__ __forceinline__ void ldsm4(uint32_t& r0, uint32_t& r1, uint32_t& r2, uint32_t& r3,
                                      uint32_t a) {
    asm volatile("ldmatrix.sync.aligned.m8n8.x4.shared.b16 {%0,%1,%2,%3}, [%4];"
                 : "=r"(r0), "=r"(r1), "=r"(r2), "=r"(r3) : "r"(a));
}
__device__ __forceinline__ void mma16816(float* d, uint32_t a0, uint32_t a1, uint32_t a2,
                                         uint32_t a3, uint32_t b0, uint32_t b1) {
    asm volatile(
        "mma.sync.aligned.m16n8k16.row.col.f32.f16.f16.f32 "
        "{%0,%1,%2,%3}, {%4,%5,%6,%7}, {%8,%9}, {%0,%1,%2,%3};"
        : "+f"(d[0]), "+f"(d[1]), "+f"(d[2]), "+f"(d[3])
        : "r"(a0), "r"(a1), "r"(a2), "r"(a3), "r"(b0), "r"(b1));
}
// swizzled smem addr: rows of 128 fp16 (256B = 16 chunks of 16B), chunk ^= row&7
__device__ __forceinline__ uint32_t smaddr(uint32_t base, int row, int c) {
    return base + row * 256 + (((uint32_t)(c ^ (row & 7))) << 4);
}

// ---------------- K0: precompute Rot matrices (batch-invariant) ----------------
__global__ void k0_rot(const float* __restrict__ qw) {
    int t = threadIdx.x;
    if (t >= 18) return;
    float phi = qw[t * 3 + 0], th = qw[t * 3 + 1], om = qw[t * 3 + 2];
    float c = cosf(th * 0.5f), s = sinf(th * 0.5f);
    float ap = -(phi + om) * 0.5f, am = -(phi - om) * 0.5f;
    float sp, cp, sm, cm;
    sincosf(ap, &sp, &cp);
    sincosf(am, &sm, &cm);
    float* r = g_rot + t * 8;
    r[0] = cp * c;  r[1] = sp * c;
    r[2] = -cm * s; r[3] = sm * s;
    r[4] = cm * s;  r[5] = sm * s;
    r[6] = cp * c;  r[7] = -sp * c;
}

// ---------------- K0b: transpose head_w2 [128,1296] -> fp16 [1296,128] ----------------
__global__ void k_w2split(const float* __restrict__ w2) {
    int i = blockIdx.x * blockDim.x + threadIdx.x;
    if (i >= 1296 * 128) return;
    int n = i >> 7, k = i & 127;
    g_bh[i] = __float2half_rn(w2[k * 1296 + n]);
}

// ---------------- K1: encoder  x[B,512] -> angles[B,6] ----------------
extern __shared__ float sw1[];  // 512*32 floats

__global__ void k1_encoder(const float* __restrict__ x,
                           const float* __restrict__ w1,
                           const float* __restrict__ b1,
                           const float* __restrict__ w2,
                           const float* __restrict__ b2, int B) {
    const float4* w1v = (const float4*)w1;
    float4* sv = (float4*)sw1;
    for (int i = threadIdx.x; i < (512 * 32) / 4; i += blockDim.x) sv[i] = w1v[i];
    __syncthreads();

    int s = blockIdx.x * blockDim.x + threadIdx.x;
    if (s >= B) return;

    const float4* xr = (const float4*)(x + (size_t)s * 512);
    ull acc[16];
#pragma unroll
    for (int p = 0; p < 16; p++) acc[p] = f2pack(b1[2 * p], b1[2 * p + 1]);

    for (int k4 = 0; k4 < 128; k4++) {
        float4 xv = xr[k4];
        float xs4[4] = {xv.x, xv.y, xv.z, xv.w};
#pragma unroll
        for (int u = 0; u < 4; u++) {
            ull xd = f2pack(xs4[u], xs4[u]);
            const ulonglong2* wr = (const ulonglong2*)(sw1 + (k4 * 4 + u) * 32);
#pragma unroll
            for (int p2 = 0; p2 < 8; p2++) {
                ulonglong2 wp = wr[p2];
                acc[2 * p2]     = ffma2(xd, wp.x, acc[2 * p2]);
                acc[2 * p2 + 1] = ffma2(xd, wp.y, acc[2 * p2 + 1]);
            }
        }
    }
    float h[32];
#pragma unroll
    for (int p = 0; p < 16; p++) {
        float a, b;
        f2unpack(acc[p], a, b);
        h[2 * p] = tanhf(a);
        h[2 * p + 1] = tanhf(b);
    }
#pragma unroll
    for (int i = 0; i < 6; i++) {
        float a = b2[i];
#pragma unroll
        for (int j = 0; j < 32; j++) a += h[j] * w2[j * 6 + i];
        g_angles[s * 6 + i] = a;
    }
}

// ---------------- K2: quantum circuit — 4 samples/warp, 8 lanes/sample, 8 amps/lane ----
// amp index a = (l3<<3) | j, l3 = lane&7, j = local reg index.
// qubit q <-> amp bit (5-q): q0,q1,q2 -> lane bits (masks 4,2,1); q3,q4,q5 -> local bits 2,1,0.
__device__ __forceinline__ float2 shflx(float2 v, int m) {
    float2 r;
    r.x = __shfl_xor_sync(0xffffffffu, v.x, m);
    r.y = __shfl_xor_sync(0xffffffffu, v.y, m);
    return r;
}
__device__ __forceinline__ float2 cmul(float2 a, float2 b) {
    return make_float2(a.x * b.x - a.y * b.y, a.x * b.y + a.y * b.x);
}
__device__ __forceinline__ float2 cmadd(float2 a, float2 b, float2 acc) {
    return make_float2(acc.x + a.x * b.x - a.y * b.y, acc.y + a.x * b.y + a.y * b.x);
}

__global__ void k2_circuit(const float* __restrict__ hw1,
                           const float* __restrict__ hb1, int B) {
    int gt = blockIdx.x * blockDim.x + threadIdx.x;
    int warp = gt >> 5, lane = gt & 31;
    int l3 = lane & 7;
    int s = warp * 4 + (lane >> 3);
    if (s >= B) return;

    float cs[6], sn[6];
#pragma unroll
    for (int q = 0; q < 6; q++) {
        float a = g_angles[s * 6 + q];
        __sincosf(0.5f * a, &sn[q], &cs[q]);
    }

    float2 A[8];
#pragma unroll
    for (int j = 0; j < 8; j++) A[j] = make_float2(0.f, 0.f);
    if (l3 == 0) A[0].x = 1.f;

#pragma unroll
    for (int L = 0; L < 3; L++) {
        // fused gates G_q = Rot_q * RY(a_q)
#pragma unroll
        for (int q = 0; q < 6; q++) {
            const ull* up = (const ull*)(g_rot + (L * 6 + q) * 8);
            ull u01 = up[0], u23 = up[1], u45 = up[2], u67 = up[3];
            float c = cs[q], s2 = sn[q];
            ull cp = f2pack(c, c), sp = f2pack(s2, s2), sn2 = f2pack(-s2, -s2);
            float2 f00, f01, f10, f11;
            f2unpack(ffma2(u23, sp, fmul2(u01, cp)), f00.x, f00.y);
            f2unpack(ffma2(u01, sn2, fmul2(u23, cp)), f01.x, f01.y);
            f2unpack(ffma2(u67, sp, fmul2(u45, cp)), f10.x, f10.y);
            f2unpack(ffma2(u45, sn2, fmul2(u67, cp)), f11.x, f11.y);

            if (q <= 2) {
                int m = 4 >> q;  // q0->4, q1->2, q2->1
                bool hi = (l3 & m) != 0;
                float2 ua = hi ? f11 : f00;
                float2 ub = hi ? f10 : f01;
#pragma unroll
                for (int j = 0; j < 8; j++) {
                    float2 P = shflx(A[j], m);
                    A[j] = cmadd(ub, P, cmul(ua, A[j]));
                }
            } else {
                int lb = 5 - q;  // q3->2, q4->1, q5->0
                int st = 1 << lb;
#pragma unroll
                for (int i0 = 0; i0 < 8; i0++) {
                    if (i0 & st) continue;
                    int i1 = i0 | st;
                    float2 n0 = cmadd(f01, A[i1], cmul(f00, A[i0]));
                    float2 n1 = cmadd(f11, A[i1], cmul(f10, A[i0]));
                    A[i0] = n0; A[i1] = n1;
                }
            }
        }
        // CNOT(0,1): ctrl l3b2, tgt l3b1 (shfl mask 2)
        {
#pragma unroll
            for (int j = 0; j < 8; j++) {
                float2 P = shflx(A[j], 2);
                if (l3 & 4) A[j] = P;
            }
        }
        // CNOT(2,3): ctrl l3b0, tgt j bit2 (local swap)
        if (l3 & 1) {
#pragma unroll
            for (int j = 0; j < 4; j++) { float2 t = A[j]; A[j] = A[j + 4]; A[j + 4] = t; }
        }
        // CNOT(4,5): ctrl j bit1, tgt j bit0 (local)
        { float2 t = A[2]; A[2] = A[3]; A[3] = t; }
        { float2 t = A[6]; A[6] = A[7]; A[7] = t; }
        // CNOT(1,2): ctrl l3b1, tgt l3b0 (shfl mask 1)
        {
#pragma unroll
            for (int j = 0; j < 8; j++) {
                float2 P = shflx(A[j], 1);
                if (l3 & 2) A[j] = P;
            }
        }
        // CNOT(3,4): ctrl j bit2, tgt j bit1 (local)
        { float2 t = A[4]; A[4] = A[6]; A[6] = t; }
        { float2 t = A[5]; A[5] = A[7]; A[7] = t; }
        // CNOT(5,0): ctrl j bit0, tgt l3b2 (shfl mask 4, odd j)
        {
            A[1] = shflx(A[1], 4);
            A[3] = shflx(A[3], 4);
            A[5] = shflx(A[5], 4);
            A[7] = shflx(A[7], 4);
        }
    }

    // expvals
    float p[8];
#pragma unroll
    for (int j = 0; j < 8; j++) p[j] = A[j].x * A[j].x + A[j].y * A[j].y;
    float sum = (p[0] + p[1]) + (p[2] + p[3]) + (p[4] + p[5]) + (p[6] + p[7]);
    float z[6];
    z[0] = (l3 & 4) ? -sum : sum;
    z[1] = (l3 & 2) ? -sum : sum;
    z[2] = (l3 & 1) ? -sum : sum;
    z[3] = sum - 2.f * ((p[4] + p[5]) + (p[6] + p[7]));
    z[4] = sum - 2.f * ((p[2] + p[3]) + (p[6] + p[7]));
    z[5] = sum - 2.f * ((p[1] + p[3]) + (p[5] + p[7]));
#pragma unroll
    for (int off = 4; off; off >>= 1) {
#pragma unroll
        for (int q = 0; q < 6; q++) z[q] += __shfl_xor_sync(0xffffffffu, z[q], off);
    }

    // head layer 1: lane handles 16 outputs j = l3*16 .. +15
    __half hv[16];
#pragma unroll
    for (int u = 0; u < 16; u++) {
        int j = l3 * 16 + u;
        float a = hb1[j];
#pragma unroll
        for (int i = 0; i < 6; i++) a += z[i] * hw1[i * 128 + j];
        hv[u] = __float2half_rn(fmaxf(a, 0.f));
    }
    uint4* dst = (uint4*)(g_af + (size_t)s * 128 + l3 * 16);
    dst[0] = *(uint4*)&hv[0];
    dst[1] = *(uint4*)&hv[8];
}

// ---------------- K3: HMMA fp16 GEMM  out = A[B,128] @ w2[128,1296] + b2 ----
// CTA tile 128(M) x 144(N), K=128 in smem. warp w -> rows [16w,16w+16), 18 n-frags.
#define K3_SMEM (32768 + 36864)

__global__ __launch_bounds__(256, 2)
void k3_mma(const float* __restrict__ b2, float* __restrict__ out, int B) {
    extern __shared__ char sm3[];
    __half* sA  = (__half*)sm3;            // 128 x 128
    __half* sBh = (__half*)(sm3 + 32768);  // 144 x 128

    int tid = threadIdx.x, lane = tid & 31, wid = tid >> 5;
    int n0 = blockIdx.x * 144;
    int m0 = blockIdx.y * 128;

    // stage A (swizzled 16B chunks)
    const uint4* gA = (const uint4*)g_af + (size_t)m0 * 16;
    uint4* dA = (uint4*)sA;
#pragma unroll
    for (int it = 0; it < 8; it++) {
        int i = it * 256 + tid;
        int r = i >> 4, c = i & 15;
        dA[r * 16 + (c ^ (r & 7))] = gA[i];
    }
    // stage B (144 rows x 16 chunks = 2304)
    const uint4* gBh = (const uint4*)g_bh + (size_t)n0 * 16;
    uint4* dBh = (uint4*)sBh;
#pragma unroll
    for (int it = 0; it < 9; it++) {
        int i = it * 256 + tid;
        int r = i >> 4, c = i & 15;
        dBh[r * 16 + (c ^ (r & 7))] = gBh[i];
    }
    __syncthreads();

    uint32_t sAb = smem_u32(sA), sBhb = smem_u32(sBh);
    int la = lane & 7, hb = (lane >> 3) & 1, hc = lane >> 4;
    int arow = wid * 16 + la + (hb << 3);
    int brow = la + (hb << 3);

    float acc[18][4];
#pragma unroll
    for (int j = 0; j < 18; j++)
#pragma unroll
        for (int v = 0; v < 4; v++) acc[j][v] = 0.f;

#pragma unroll
    for (int ks = 0; ks < 8; ks++) {
        int ca = 2 * ks + hc;
        uint32_t a0, a1, a2, a3;
        ldsm4(a0, a1, a2, a3, smaddr(sAb, arow, ca));

#pragma unroll
        for (int p = 0; p < 9; p++) {
            uint32_t r0, r1, r2, r3;
            ldsm4(r0, r1, r2, r3, smaddr(sBhb, p * 16 + brow, ca));
            mma16816(acc[2 * p],     a0, a1, a2, a3, r0, r2);
            mma16816(acc[2 * p + 1], a0, a1, a2, a3, r1, r3);
        }
    }

    // epilogue: d0,d1 -> row lane>>2; d2,d3 -> row+8; cols 2*(lane&3)+{0,1} per frag
    int orow0 = m0 + wid * 16 + (lane >> 2);
    float* op = out + (size_t)orow0 * 1296 + n0 + 2 * (lane & 3);
    const float* bp = b2 + n0 + 2 * (lane & 3);
#pragma unroll
    for (int j = 0; j < 18; j++) {
        float2 bias = *(const float2*)(bp + 8 * j);
        float2 v0 = make_float2(acc[j][0] + bias.x, acc[j][1] + bias.y);
        float2 v1 = make_float2(acc[j][2] + bias.x, acc[j][3] + bias.y);
        *(float2*)(op + 8 * j) = v0;
        *(float2*)(op + 8 * j + 8 * 1296) = v1;
    }
}

// ---------------- launch ----------------
extern "C" void kernel_launch(void* const* d_in, const int* in_sizes, int n_in,
                              void* d_out, int out_size) {
    const float* x   = (const float*)d_in[0];
    const float* ew1 = (const float*)d_in[1];
    const float* eb1 = (const float*)d_in[2];
    const float* ew2 = (const float*)d_in[3];
    const float* eb2 = (const float*)d_in[4];
    const float* qw  = (const float*)d_in[5];
    const float* hw1 = (const float*)d_in[6];
    const float* hb1 = (const float*)d_in[7];
    const float* hw2 = (const float*)d_in[8];
    const float* hb2 = (const float*)d_in[9];
    float* out = (float*)d_out;

    int B = in_sizes[0] / 512;

    cudaFuncSetAttribute(k1_encoder, cudaFuncAttributeMaxDynamicSharedMemorySize, 65536);
    cudaFuncSetAttribute(k3_mma, cudaFuncAttributeMaxDynamicSharedMemorySize, K3_SMEM);

    k0_rot<<<1, 32>>>(qw);
    k_w2split<<<(1296 * 128 + 255) / 256, 256>>>(hw2);
    k1_encoder<<<(B + 127) / 128, 128, 65536>>>(x, ew1, eb1, ew2, eb2, B);
    k2_circuit<<<(B * 8 + 255) / 256, 256>>>(hw1, hb1, B);
    dim3 g3(9, B / 128);
    k3_mma<<<g3, 256, K3_SMEM>>>(hb2, out, B);
}

// round 7
// speedup vs baseline: 2.9861x; 1.2356x over previous
#include <cuda_runtime.h>
#include <cuda_fp16.h>
#include <cstdint>

typedef unsigned long long ull;

#define BMAX 32768

// ---------------- scratch (static device globals: no allocation) ----------------
__device__ float g_angles[BMAX * 6];
__device__ __align__(16) float g_rot[18 * 8];
__device__ __align__(16) __half g_af[(size_t)BMAX * 128];  // A (activations) fp16
__device__ __align__(16) __half g_bh[1296 * 128];          // w2^T fp16 [N,K]
__device__ __align__(16) __half g_w1p[32 * 32 * 4 * 8];    // enc_w1 packed frags hi/lo

// ---------------- f32x2 packed helpers ----------------
__device__ __forceinline__ ull f2pack(float a, float b) {
    ull r;
    asm("mov.b64 %0, {%1, %2};" : "=l"(r) : "r"(__float_as_uint(a)), "r"(__float_as_uint(b)));
    return r;
}
__device__ __forceinline__ void f2unpack(ull v, float& a, float& b) {
    unsigned int lo, hi;
    asm("mov.b64 {%0, %1}, %2;" : "=r"(lo), "=r"(hi) : "l"(v));
    a = __uint_as_float(lo); b = __uint_as_float(hi);
}
__device__ __forceinline__ ull ffma2(ull a, ull b, ull c) {
    ull d;
    asm("fma.rn.f32x2 %0, %1, %2, %3;" : "=l"(d) : "l"(a), "l"(b), "l"(c));
    return d;
}
__device__ __forceinline__ ull fmul2(ull a, ull b) {
    ull d;
    asm("mul.rn.f32x2 %0, %1, %2;" : "=l"(d) : "l"(a), "l"(b));
    return d;
}

// ---------------- mma/ldmatrix helpers ----------------
__device__ __forceinline__ uint32_t smem_u32(const void* p) {
    uint32_t a;
    asm("{ .reg .u64 t; cvta.to.shared.u64 t, %1; cvt.u32.u64 %0, t; }" : "=r"(a) : "l"(p));
    return a;
}
__device__ __forceinline__ void ldsm4(uint32_t& r0, uint32_t& r1, uint32_t& r2, uint32_t& r3,
                                      uint32_t a) {
    asm volatile("ldmatrix.sync.aligned.m8n8.x4.shared.b16 {%0,%1,%2,%3}, [%4];"
                 : "=r"(r0), "=r"(r1), "=r"(r2), "=r"(r3) : "r"(a));
}
__device__ __forceinline__ void mma16816(float* d, uint32_t a0, uint32_t a1, uint32_t a2,
                                         uint32_t a3, uint32_t b0, uint32_t b1) {
    asm volatile(
        "mma.sync.aligned.m16n8k16.row.col.f32.f16.f16.f32 "
        "{%0,%1,%2,%3}, {%4,%5,%6,%7}, {%8,%9}, {%0,%1,%2,%3};"
        : "+f"(d[0]), "+f"(d[1]), "+f"(d[2]), "+f"(d[3])
        : "r"(a0), "r"(a1), "r"(a2), "r"(a3), "r"(b0), "r"(b1));
}
// swizzled smem addr: rows of 128 fp16 (256B = 16 chunks of 16B), chunk ^= row&7
__device__ __forceinline__ uint32_t smaddr(uint32_t base, int row, int c) {
    return base + row * 256 + (((uint32_t)(c ^ (row & 7))) << 4);
}
__device__ __forceinline__ uint32_t h2pack(float a, float b) {
    __half2 h = __floats2half2_rn(a, b);
    return *(uint32_t*)&h;
}

// ---------------- K0: precompute Rot matrices (batch-invariant) ----------------
__global__ void k0_rot(const float* __restrict__ qw) {
    int t = threadIdx.x;
    if (t >= 18) return;
    float phi = qw[t * 3 + 0], th = qw[t * 3 + 1], om = qw[t * 3 + 2];
    float c = cosf(th * 0.5f), s = sinf(th * 0.5f);
    float ap = -(phi + om) * 0.5f, am = -(phi - om) * 0.5f;
    float sp, cp, sm, cm;
    sincosf(ap, &sp, &cp);
    sincosf(am, &sm, &cm);
    float* r = g_rot + t * 8;
    r[0] = cp * c;  r[1] = sp * c;
    r[2] = -cm * s; r[3] = sm * s;
    r[4] = cm * s;  r[5] = sm * s;
    r[6] = cp * c;  r[7] = -sp * c;
}

// ---------------- K0b: transpose head_w2 [128,1296] -> fp16 [1296,128] ----------------
__global__ void k_w2split(const float* __restrict__ w2) {
    int i = blockIdx.x * blockDim.x + threadIdx.x;
    if (i >= 1296 * 128) return;
    int n = i >> 7, k = i & 127;
    g_bh[i] = __float2half_rn(w2[k * 1296 + n]);
}

// ---------------- K0c: pack enc_w1 [512,32] into mma-fragment order, fp16 hi/lo ----
// record (n, ks, q): halves {hi(kc),hi(kc+1),hi(kc+8),hi(kc+9), lo(...x4)}, kc=16ks+2q
__global__ void k_w1pack(const float* __restrict__ w1) {
    int i = blockIdx.x * blockDim.x + threadIdx.x;
    if (i >= 4096) return;
    int q = i & 3, ks = (i >> 2) & 31, n = i >> 7;
    int kc = ks * 16 + 2 * q;
    float v0 = w1[(kc + 0) * 32 + n];
    float v1 = w1[(kc + 1) * 32 + n];
    float v2 = w1[(kc + 8) * 32 + n];
    float v3 = w1[(kc + 9) * 32 + n];
    __half h[8];
    h[0] = __float2half_rn(v0); h[1] = __float2half_rn(v1);
    h[2] = __float2half_rn(v2); h[3] = __float2half_rn(v3);
    h[4] = __float2half_rn(v0 - __half2float(h[0]));
    h[5] = __float2half_rn(v1 - __half2float(h[1]));
    h[6] = __float2half_rn(v2 - __half2float(h[2]));
    h[7] = __float2half_rn(v3 - __half2float(h[3]));
    *(uint4*)(g_w1p + (size_t)i * 8) = *(uint4*)h;
}

// ---------------- K1: encoder via HMMA, 3-pass split (xh*wh + xh*wl + xl*wh) ----------
// warp -> 16 rows. A frags built from global float2 loads; B frags from g_w1p (L1-hot).
__global__ __launch_bounds__(256)
void k1_encoder(const float* __restrict__ x,
                const float* __restrict__ b1,
                const float* __restrict__ w2,
                const float* __restrict__ b2, int B) {
    int tid = threadIdx.x, lane = tid & 31, wid = tid >> 5;
    int m0 = blockIdx.x * 128 + wid * 16;
    int g = lane >> 2, q = lane & 3;
    const float* xr0 = x + (size_t)(m0 + g) * 512;
    const float* xr1 = x + (size_t)(m0 + g + 8) * 512;

    float acc[4][4];
#pragma unroll
    for (int nf = 0; nf < 4; nf++)
#pragma unroll
        for (int v = 0; v < 4; v++) acc[nf][v] = 0.f;

#pragma unroll 4
    for (int ks = 0; ks < 32; ks++) {
        int kc = ks * 16 + 2 * q;
        float2 xa = *(const float2*)(xr0 + kc);
        float2 xb = *(const float2*)(xr1 + kc);
        float2 xc = *(const float2*)(xr0 + kc + 8);
        float2 xd = *(const float2*)(xr1 + kc + 8);

        uint32_t ah0 = h2pack(xa.x, xa.y), ah1 = h2pack(xb.x, xb.y);
        uint32_t ah2 = h2pack(xc.x, xc.y), ah3 = h2pack(xd.x, xd.y);
        __half2 ha0 = *(__half2*)&ah0, ha1 = *(__half2*)&ah1;
        __half2 ha2 = *(__half2*)&ah2, ha3 = *(__half2*)&ah3;
        uint32_t al0 = h2pack(xa.x - __low2float(ha0), xa.y - __high2float(ha0));
        uint32_t al1 = h2pack(xb.x - __low2float(ha1), xb.y - __high2float(ha1));
        uint32_t al2 = h2pack(xc.x - __low2float(ha2), xc.y - __high2float(ha2));
        uint32_t al3 = h2pack(xd.x - __low2float(ha3), xd.y - __high2float(ha3));

#pragma unroll
        for (int nf = 0; nf < 4; nf++) {
            int n = nf * 8 + g;
            uint4 bv = *(const uint4*)(g_w1p + (size_t)(((n * 32 + ks) * 4 + q)) * 8);
            mma16816(acc[nf], ah0, ah1, ah2, ah3, bv.x, bv.y);  // xh * wh
            mma16816(acc[nf], ah0, ah1, ah2, ah3, bv.z, bv.w);  // xh * wl
            mma16816(acc[nf], al0, al1, al2, al3, bv.x, bv.y);  // xl * wh
        }
    }

    // h = tanh(preact + b1); then angles = h @ w2 + b2 (per-row, lanewise partials)
    float pr0[6], pr1[6];
#pragma unroll
    for (int i = 0; i < 6; i++) { pr0[i] = 0.f; pr1[i] = 0.f; }

#pragma unroll
    for (int nf = 0; nf < 4; nf++) {
        int c0 = nf * 8 + 2 * q;
        float bb0 = b1[c0], bb1 = b1[c0 + 1];
        float h00 = tanhf(acc[nf][0] + bb0);
        float h01 = tanhf(acc[nf][1] + bb1);
        float h10 = tanhf(acc[nf][2] + bb0);
        float h11 = tanhf(acc[nf][3] + bb1);
#pragma unroll
        for (int i = 0; i < 6; i++) {
            float w0 = w2[c0 * 6 + i], w1v = w2[(c0 + 1) * 6 + i];
            pr0[i] += h00 * w0 + h01 * w1v;
            pr1[i] += h10 * w0 + h11 * w1v;
        }
    }
#pragma unroll
    for (int m = 1; m <= 2; m <<= 1) {
#pragma unroll
        for (int i = 0; i < 6; i++) {
            pr0[i] += __shfl_xor_sync(0xffffffffu, pr0[i], m);
            pr1[i] += __shfl_xor_sync(0xffffffffu, pr1[i], m);
        }
    }
    if (q == 0) {
#pragma unroll
        for (int i = 0; i < 6; i++) {
            g_angles[(size_t)(m0 + g) * 6 + i] = pr0[i] + b2[i];
            g_angles[(size_t)(m0 + g + 8) * 6 + i] = pr1[i] + b2[i];
        }
    }
}

// ---------------- K2: quantum circuit — 4 samples/warp, 8 lanes/sample, 8 amps/lane ----
__device__ __forceinline__ float2 shflx(float2 v, int m) {
    float2 r;
    r.x = __shfl_xor_sync(0xffffffffu, v.x, m);
    r.y = __shfl_xor_sync(0xffffffffu, v.y, m);
    return r;
}
__device__ __forceinline__ float2 cmul(float2 a, float2 b) {
    return make_float2(a.x * b.x - a.y * b.y, a.x * b.y + a.y * b.x);
}
__device__ __forceinline__ float2 cmadd(float2 a, float2 b, float2 acc) {
    return make_float2(acc.x + a.x * b.x - a.y * b.y, acc.y + a.x * b.y + a.y * b.x);
}

__global__ void k2_circuit(const float* __restrict__ hw1,
                           const float* __restrict__ hb1, int B) {
    int gt = blockIdx.x * blockDim.x + threadIdx.x;
    int warp = gt >> 5, lane = gt & 31;
    int l3 = lane & 7;
    int s = warp * 4 + (lane >> 3);
    if (s >= B) return;

    float cs[6], sn[6];
#pragma unroll
    for (int q = 0; q < 6; q++) {
        float a = g_angles[s * 6 + q];
        __sincosf(0.5f * a, &sn[q], &cs[q]);
    }

    float2 A[8];
#pragma unroll
    for (int j = 0; j < 8; j++) A[j] = make_float2(0.f, 0.f);
    if (l3 == 0) A[0].x = 1.f;

#pragma unroll
    for (int L = 0; L < 3; L++) {
#pragma unroll
        for (int q = 0; q < 6; q++) {
            const ull* up = (const ull*)(g_rot + (L * 6 + q) * 8);
            ull u01 = up[0], u23 = up[1], u45 = up[2], u67 = up[3];
            float c = cs[q], s2 = sn[q];
            ull cp = f2pack(c, c), sp = f2pack(s2, s2), sn2 = f2pack(-s2, -s2);
            float2 f00, f01, f10, f11;
            f2unpack(ffma2(u23, sp, fmul2(u01, cp)), f00.x, f00.y);
            f2unpack(ffma2(u01, sn2, fmul2(u23, cp)), f01.x, f01.y);
            f2unpack(ffma2(u67, sp, fmul2(u45, cp)), f10.x, f10.y);
            f2unpack(ffma2(u45, sn2, fmul2(u67, cp)), f11.x, f11.y);

            if (q <= 2) {
                int m = 4 >> q;
                bool hi = (l3 & m) != 0;
                float2 ua = hi ? f11 : f00;
                float2 ub = hi ? f10 : f01;
#pragma unroll
                for (int j = 0; j < 8; j++) {
                    float2 P = shflx(A[j], m);
                    A[j] = cmadd(ub, P, cmul(ua, A[j]));
                }
            } else {
                int lb = 5 - q;
                int st = 1 << lb;
#pragma unroll
                for (int i0 = 0; i0 < 8; i0++) {
                    if (i0 & st) continue;
                    int i1 = i0 | st;
                    float2 n0 = cmadd(f01, A[i1], cmul(f00, A[i0]));
                    float2 n1 = cmadd(f11, A[i1], cmul(f10, A[i0]));
                    A[i0] = n0; A[i1] = n1;
                }
            }
        }
        // CNOT(0,1)
        {
#pragma unroll
            for (int j = 0; j < 8; j++) {
                float2 P = shflx(A[j], 2);
                if (l3 & 4) A[j] = P;
            }
        }
        // CNOT(2,3)
        if (l3 & 1) {
#pragma unroll
            for (int j = 0; j < 4; j++) { float2 t = A[j]; A[j] = A[j + 4]; A[j + 4] = t; }
        }
        // CNOT(4,5)
        { float2 t = A[2]; A[2] = A[3]; A[3] = t; }
        { float2 t = A[6]; A[6] = A[7]; A[7] = t; }
        // CNOT(1,2)
        {
#pragma unroll
            for (int j = 0; j < 8; j++) {
                float2 P = shflx(A[j], 1);
                if (l3 & 2) A[j] = P;
            }
        }
        // CNOT(3,4)
        { float2 t = A[4]; A[4] = A[6]; A[6] = t; }
        { float2 t = A[5]; A[5] = A[7]; A[7] = t; }
        // CNOT(5,0)
        {
            A[1] = shflx(A[1], 4);
            A[3] = shflx(A[3], 4);
            A[5] = shflx(A[5], 4);
            A[7] = shflx(A[7], 4);
        }
    }

    float p[8];
#pragma unroll
    for (int j = 0; j < 8; j++) p[j] = A[j].x * A[j].x + A[j].y * A[j].y;
    float sum = (p[0] + p[1]) + (p[2] + p[3]) + (p[4] + p[5]) + (p[6] + p[7]);
    float z[6];
    z[0] = (l3 & 4) ? -sum : sum;
    z[1] = (l3 & 2) ? -sum : sum;
    z[2] = (l3 & 1) ? -sum : sum;
    z[3] = sum - 2.f * ((p[4] + p[5]) + (p[6] + p[7]));
    z[4] = sum - 2.f * ((p[2] + p[3]) + (p[6] + p[7]));
    z[5] = sum - 2.f * ((p[1] + p[3]) + (p[5] + p[7]));
#pragma unroll
    for (int off = 4; off; off >>= 1) {
#pragma unroll
        for (int q = 0; q < 6; q++) z[q] += __shfl_xor_sync(0xffffffffu, z[q], off);
    }

    __half hv[16];
#pragma unroll
    for (int u = 0; u < 16; u++) {
        int j = l3 * 16 + u;
        float a = hb1[j];
#pragma unroll
        for (int i = 0; i < 6; i++) a += z[i] * hw1[i * 128 + j];
        hv[u] = __float2half_rn(fmaxf(a, 0.f));
    }
    uint4* dst = (uint4*)(g_af + (size_t)s * 128 + l3 * 16);
    dst[0] = *(uint4*)&hv[0];
    dst[1] = *(uint4*)&hv[8];
}

// ---------------- K3: HMMA fp16 GEMM  out = A[B,128] @ w2[128,1296] + b2 ----
#define K3_SMEM (32768 + 36864)

__global__ __launch_bounds__(256, 2)
void k3_mma(const float* __restrict__ b2, float* __restrict__ out, int B) {
    extern __shared__ char sm3[];
    __half* sA  = (__half*)sm3;            // 128 x 128
    __half* sBh = (__half*)(sm3 + 32768);  // 144 x 128

    int tid = threadIdx.x, lane = tid & 31, wid = tid >> 5;
    int n0 = blockIdx.x * 144;
    int m0 = blockIdx.y * 128;

    const uint4* gA = (const uint4*)g_af + (size_t)m0 * 16;
    uint4* dA = (uint4*)sA;
#pragma unroll
    for (int it = 0; it < 8; it++) {
        int i = it * 256 + tid;
        int r = i >> 4, c = i & 15;
        dA[r * 16 + (c ^ (r & 7))] = gA[i];
    }
    const uint4* gBh = (const uint4*)g_bh + (size_t)n0 * 16;
    uint4* dBh = (uint4*)sBh;
#pragma unroll
    for (int it = 0; it < 9; it++) {
        int i = it * 256 + tid;
        int r = i >> 4, c = i & 15;
        dBh[r * 16 + (c ^ (r & 7))] = gBh[i];
    }
    __syncthreads();

    uint32_t sAb = smem_u32(sA), sBhb = smem_u32(sBh);
    int la = lane & 7, hb = (lane >> 3) & 1, hc = lane >> 4;
    int arow = wid * 16 + la + (hb << 3);
    int brow = la + (hb << 3);

    float acc[18][4];
#pragma unroll
    for (int j = 0; j < 18; j++)
#pragma unroll
        for (int v = 0; v < 4; v++) acc[j][v] = 0.f;

#pragma unroll
    for (int ks = 0; ks < 8; ks++) {
        int ca = 2 * ks + hc;
        uint32_t a0, a1, a2, a3;
        ldsm4(a0, a1, a2, a3, smaddr(sAb, arow, ca));

#pragma unroll
        for (int p = 0; p < 9; p++) {
            uint32_t r0, r1, r2, r3;
            ldsm4(r0, r1, r2, r3, smaddr(sBhb, p * 16 + brow, ca));
            mma16816(acc[2 * p],     a0, a1, a2, a3, r0, r2);
            mma16816(acc[2 * p + 1], a0, a1, a2, a3, r1, r3);
        }
    }

    int orow0 = m0 + wid * 16 + (lane >> 2);
    float* op = out + (size_t)orow0 * 1296 + n0 + 2 * (lane & 3);
    const float* bp = b2 + n0 + 2 * (lane & 3);
#pragma unroll
    for (int j = 0; j < 18; j++) {
        float2 bias = *(const float2*)(bp + 8 * j);
        float2 v0 = make_float2(acc[j][0] + bias.x, acc[j][1] + bias.y);
        float2 v1 = make_float2(acc[j][2] + bias.x, acc[j][3] + bias.y);
        *(float2*)(op + 8 * j) = v0;
        *(float2*)(op + 8 * j + 8 * 1296) = v1;
    }
}

// ---------------- launch ----------------
extern "C" void kernel_launch(void* const* d_in, const int* in_sizes, int n_in,
                              void* d_out, int out_size) {
    const float* x   = (const float*)d_in[0];
    const float* ew1 = (const float*)d_in[1];
    const float* eb1 = (const float*)d_in[2];
    const float* ew2 = (const float*)d_in[3];
    const float* eb2 = (const float*)d_in[4];
    const float* qw  = (const float*)d_in[5];
    const float* hw1 = (const float*)d_in[6];
    const float* hb1 = (const float*)d_in[7];
    const float* hw2 = (const float*)d_in[8];
    const float* hb2 = (const float*)d_in[9];
    float* out = (float*)d_out;

    int B = in_sizes[0] / 512;

    cudaFuncSetAttribute(k3_mma, cudaFuncAttributeMaxDynamicSharedMemorySize, K3_SMEM);

    k0_rot<<<1, 32>>>(qw);
    k_w1pack<<<16, 256>>>(ew1);
    k_w2split<<<(1296 * 128 + 255) / 256, 256>>>(hw2);
    k1_encoder<<<B / 128, 256>>>(x, eb1, ew2, eb2, B);
    k2_circuit<<<(B * 8 + 255) / 256, 256>>>(hw1, hb1, B);
    dim3 g3(9, B / 128);
    k3_mma<<<g3, 256, K3_SMEM>>>(hb2, out, B);
}

// round 8
// speedup vs baseline: 3.1599x; 1.0582x over previous
#include <cuda_runtime.h>
#include <cuda_fp16.h>
#include <cstdint>

typedef unsigned long long ull;

#define BMAX 32768

// ---------------- scratch (static device globals: no allocation) ----------------
__device__ float g_angles[BMAX * 6];
__device__ __align__(16) float g_rot[18 * 8];
__device__ __align__(16) __half g_af[(size_t)BMAX * 128];  // A (activations) fp16
__device__ __align__(16) __half g_bh[1296 * 128];          // w2^T fp16 [N,K]
__device__ __align__(16) __half g_w1p[32 * 32 * 4 * 8];    // enc_w1 packed frags hi/lo

// ---------------- f32x2 packed helpers ----------------
__device__ __forceinline__ ull f2pack(float a, float b) {
    ull r;
    asm("mov.b64 %0, {%1, %2};" : "=l"(r) : "r"(__float_as_uint(a)), "r"(__float_as_uint(b)));
    return r;
}
__device__ __forceinline__ void f2unpack(ull v, float& a, float& b) {
    unsigned int lo, hi;
    asm("mov.b64 {%0, %1}, %2;" : "=r"(lo), "=r"(hi) : "l"(v));
    a = __uint_as_float(lo); b = __uint_as_float(hi);
}
__device__ __forceinline__ ull ffma2(ull a, ull b, ull c) {
    ull d;
    asm("fma.rn.f32x2 %0, %1, %2, %3;" : "=l"(d) : "l"(a), "l"(b), "l"(c));
    return d;
}
__device__ __forceinline__ ull fmul2(ull a, ull b) {
    ull d;
    asm("mul.rn.f32x2 %0, %1, %2;" : "=l"(d) : "l"(a), "l"(b));
    return d;
}

// ---------------- mma/ldmatrix helpers ----------------
__device__ __forceinline__ uint32_t smem_u32(const void* p) {
    uint32_t a;
    asm("{ .reg .u64 t; cvta.to.shared.u64 t, %1; cvt.u32.u64 %0, t; }" : "=r"(a) : "l"(p));
    return a;
}
__device__ __forceinline__ void ldsm4(uint32_t& r0, uint32_t& r1, uint32_t& r2, uint32_t& r3,
                                      uint32_t a) {
    asm volatile("ldmatrix.sync.aligned.m8n8.x4.shared.b16 {%0,%1,%2,%3}, [%4];"
                 : "=r"(r0), "=r"(r1), "=r"(r2), "=r"(r3) : "r"(a));
}
__device__ __forceinline__ void mma16816(float* d, uint32_t a0, uint32_t a1, uint32_t a2,
                                         uint32_t a3, uint32_t b0, uint32_t b1) {
    asm volatile(
        "mma.sync.aligned.m16n8k16.row.col.f32.f16.f16.f32 "
        "{%0,%1,%2,%3}, {%4,%5,%6,%7}, {%8,%9}, {%0,%1,%2,%3};"
        : "+f"(d[0]), "+f"(d[1]), "+f"(d[2]), "+f"(d[3])
        : "r"(a0), "r"(a1), "r"(a2), "r"(a3), "r"(b0), "r"(b1));
}
// swizzled smem addr: rows of 128 fp16 (256B = 16 chunks of 16B), chunk ^= row&7
__device__ __forceinline__ uint32_t smaddr(uint32_t base, int row, int c) {
    return base + row * 256 + (((uint32_t)(c ^ (row & 7))) << 4);
}
__device__ __forceinline__ uint32_t h2pack(float a, float b) {
    __half2 h = __floats2half2_rn(a, b);
    return *(uint32_t*)&h;
}

// ---------------- K0: precompute Rot matrices (batch-invariant) ----------------
__global__ void k0_rot(const float* __restrict__ qw) {
    int t = threadIdx.x;
    if (t >= 18) return;
    float phi = qw[t * 3 + 0], th = qw[t * 3 + 1], om = qw[t * 3 + 2];
    float c = cosf(th * 0.5f), s = sinf(th * 0.5f);
    float ap = -(phi + om) * 0.5f, am = -(phi - om) * 0.5f;
    float sp, cp, sm, cm;
    sincosf(ap, &sp, &cp);
    sincosf(am, &sm, &cm);
    float* r = g_rot + t * 8;
    r[0] = cp * c;  r[1] = sp * c;
    r[2] = -cm * s; r[3] = sm * s;
    r[4] = cm * s;  r[5] = sm * s;
    r[6] = cp * c;  r[7] = -sp * c;
}

// ---------------- K0b: transpose head_w2 [128,1296] -> fp16 [1296,128] ----------------
__global__ void k_w2split(const float* __restrict__ w2) {
    int i = blockIdx.x * blockDim.x + threadIdx.x;
    if (i >= 1296 * 128) return;
    int n = i >> 7, k = i & 127;
    g_bh[i] = __float2half_rn(w2[k * 1296 + n]);
}

// ---------------- K0c: pack enc_w1 [512,32] into mma-fragment order, fp16 hi/lo ----
// k-permuted map: record (n, ks, q) holds logical k = 16ks+4q+{0,1,2,3}
//   hw positions: (2q,2q+1) <- +{0,1};  (8+2q,8+2q+1) <- +{2,3}
__global__ void k_w1pack(const float* __restrict__ w1) {
    int i = blockIdx.x * blockDim.x + threadIdx.x;
    if (i >= 4096) return;
    int q = i & 3, ks = (i >> 2) & 31, n = i >> 7;
    int kc = ks * 16 + 4 * q;
    float v0 = w1[(kc + 0) * 32 + n];
    float v1 = w1[(kc + 1) * 32 + n];
    float v2 = w1[(kc + 2) * 32 + n];
    float v3 = w1[(kc + 3) * 32 + n];
    __half h[8];
    h[0] = __float2half_rn(v0); h[1] = __float2half_rn(v1);
    h[2] = __float2half_rn(v2); h[3] = __float2half_rn(v3);
    h[4] = __float2half_rn(v0 - __half2float(h[0]));
    h[5] = __float2half_rn(v1 - __half2float(h[1]));
    h[6] = __float2half_rn(v2 - __half2float(h[2]));
    h[7] = __float2half_rn(v3 - __half2float(h[3]));
    *(uint4*)(g_w1p + (size_t)i * 8) = *(uint4*)h;
}

// ---------------- K1: encoder via HMMA, 3-pass split, K-split x4 across warps ------
// CTA: 8 warps = 2 row-tiles (16 rows each) x 4 K-quarter warps. smem reduce.
__global__ __launch_bounds__(256)
void k1_encoder(const float* __restrict__ x,
                const float* __restrict__ b1,
                const float* __restrict__ w2,
                const float* __restrict__ b2, int B) {
    __shared__ float red[2][3][32][16];

    int tid = threadIdx.x, lane = tid & 31, wid = tid >> 5;
    int tile = wid >> 2, tw = wid & 3;
    int m0 = blockIdx.x * 32 + tile * 16;
    int g = lane >> 2, q = lane & 3;
    const float* xr0 = x + (size_t)(m0 + g) * 512;
    const float* xr1 = x + (size_t)(m0 + g + 8) * 512;

    float acc[4][4];
#pragma unroll
    for (int nf = 0; nf < 4; nf++)
#pragma unroll
        for (int v = 0; v < 4; v++) acc[nf][v] = 0.f;

#pragma unroll
    for (int kk = 0; kk < 8; kk++) {
        int ks = tw * 8 + kk;
        int kc = ks * 16 + 4 * q;
        float4 v0 = *(const float4*)(xr0 + kc);
        float4 v1 = *(const float4*)(xr1 + kc);

        uint32_t ah0 = h2pack(v0.x, v0.y), ah1 = h2pack(v1.x, v1.y);
        uint32_t ah2 = h2pack(v0.z, v0.w), ah3 = h2pack(v1.z, v1.w);
        __half2 t0 = *(__half2*)&ah0, t1 = *(__half2*)&ah1;
        __half2 t2 = *(__half2*)&ah2, t3 = *(__half2*)&ah3;
        uint32_t al0 = h2pack(v0.x - __low2float(t0), v0.y - __high2float(t0));
        uint32_t al1 = h2pack(v1.x - __low2float(t1), v1.y - __high2float(t1));
        uint32_t al2 = h2pack(v0.z - __low2float(t2), v0.w - __high2float(t2));
        uint32_t al3 = h2pack(v1.z - __low2float(t3), v1.w - __high2float(t3));

#pragma unroll
        for (int nf = 0; nf < 4; nf++) {
            int n = nf * 8 + g;
            uint4 bv = *(const uint4*)(g_w1p + (size_t)(((n * 32 + ks) * 4 + q)) * 8);
            mma16816(acc[nf], ah0, ah1, ah2, ah3, bv.x, bv.y);  // xh * wh
            mma16816(acc[nf], ah0, ah1, ah2, ah3, bv.z, bv.w);  // xh * wl
            mma16816(acc[nf], al0, al1, al2, al3, bv.x, bv.y);  // xl * wh
        }
    }

    // K-split reduction: warps 1-3 of each tile dump partials, warp 0 sums.
    if (tw) {
        float4* dst = (float4*)red[tile][tw - 1][lane];
#pragma unroll
        for (int nf = 0; nf < 4; nf++) dst[nf] = *(float4*)acc[nf];
    }
    __syncthreads();
    if (tw != 0) return;

#pragma unroll
    for (int w = 0; w < 3; w++) {
        const float* src = red[tile][w][lane];
#pragma unroll
        for (int nf = 0; nf < 4; nf++)
#pragma unroll
            for (int v = 0; v < 4; v++) acc[nf][v] += src[nf * 4 + v];
    }

    // h = tanh(preact + b1); then angles = h @ w2 + b2 (per-row, lanewise partials)
    float pr0[6], pr1[6];
#pragma unroll
    for (int i = 0; i < 6; i++) { pr0[i] = 0.f; pr1[i] = 0.f; }

#pragma unroll
    for (int nf = 0; nf < 4; nf++) {
        int c0 = nf * 8 + 2 * q;
        float bb0 = b1[c0], bb1 = b1[c0 + 1];
        float h00 = tanhf(acc[nf][0] + bb0);
        float h01 = tanhf(acc[nf][1] + bb1);
        float h10 = tanhf(acc[nf][2] + bb0);
        float h11 = tanhf(acc[nf][3] + bb1);
#pragma unroll
        for (int i = 0; i < 6; i++) {
            float w0 = w2[c0 * 6 + i], w1v = w2[(c0 + 1) * 6 + i];
            pr0[i] += h00 * w0 + h01 * w1v;
            pr1[i] += h10 * w0 + h11 * w1v;
        }
    }
#pragma unroll
    for (int m = 1; m <= 2; m <<= 1) {
#pragma unroll
        for (int i = 0; i < 6; i++) {
            pr0[i] += __shfl_xor_sync(0xffffffffu, pr0[i], m);
            pr1[i] += __shfl_xor_sync(0xffffffffu, pr1[i], m);
        }
    }
    if (q == 0) {
#pragma unroll
        for (int i = 0; i < 6; i++) {
            g_angles[(size_t)(m0 + g) * 6 + i] = pr0[i] + b2[i];
            g_angles[(size_t)(m0 + g + 8) * 6 + i] = pr1[i] + b2[i];
        }
    }
}

// ---------------- K2: quantum circuit — 4 samples/warp, 8 lanes/sample, 8 amps/lane ----
__device__ __forceinline__ float2 shflx(float2 v, int m) {
    float2 r;
    r.x = __shfl_xor_sync(0xffffffffu, v.x, m);
    r.y = __shfl_xor_sync(0xffffffffu, v.y, m);
    return r;
}
__device__ __forceinline__ float2 cmul(float2 a, float2 b) {
    return make_float2(a.x * b.x - a.y * b.y, a.x * b.y + a.y * b.x);
}
__device__ __forceinline__ float2 cmadd(float2 a, float2 b, float2 acc) {
    return make_float2(acc.x + a.x * b.x - a.y * b.y, acc.y + a.x * b.y + a.y * b.x);
}

__global__ void k2_circuit(const float* __restrict__ hw1,
                           const float* __restrict__ hb1, int B) {
    int gt = blockIdx.x * blockDim.x + threadIdx.x;
    int warp = gt >> 5, lane = gt & 31;
    int l3 = lane & 7;
    int s = warp * 4 + (lane >> 3);
    if (s >= B) return;

    float cs[6], sn[6];
#pragma unroll
    for (int q = 0; q < 6; q++) {
        float a = g_angles[s * 6 + q];
        __sincosf(0.5f * a, &sn[q], &cs[q]);
    }

    float2 A[8];
#pragma unroll
    for (int j = 0; j < 8; j++) A[j] = make_float2(0.f, 0.f);
    if (l3 == 0) A[0].x = 1.f;

#pragma unroll
    for (int L = 0; L < 3; L++) {
#pragma unroll
        for (int q = 0; q < 6; q++) {
            const ull* up = (const ull*)(g_rot + (L * 6 + q) * 8);
            ull u01 = up[0], u23 = up[1], u45 = up[2], u67 = up[3];
            float c = cs[q], s2 = sn[q];
            ull cp = f2pack(c, c), sp = f2pack(s2, s2), sn2 = f2pack(-s2, -s2);
            float2 f00, f01, f10, f11;
            f2unpack(ffma2(u23, sp, fmul2(u01, cp)), f00.x, f00.y);
            f2unpack(ffma2(u01, sn2, fmul2(u23, cp)), f01.x, f01.y);
            f2unpack(ffma2(u67, sp, fmul2(u45, cp)), f10.x, f10.y);
            f2unpack(ffma2(u45, sn2, fmul2(u67, cp)), f11.x, f11.y);

            if (q <= 2) {
                int m = 4 >> q;
                bool hi = (l3 & m) != 0;
                float2 ua = hi ? f11 : f00;
                float2 ub = hi ? f10 : f01;
#pragma unroll
                for (int j = 0; j < 8; j++) {
                    float2 P = shflx(A[j], m);
                    A[j] = cmadd(ub, P, cmul(ua, A[j]));
                }
            } else {
                int lb = 5 - q;
                int st = 1 << lb;
#pragma unroll
                for (int i0 = 0; i0 < 8; i0++) {
                    if (i0 & st) continue;
                    int i1 = i0 | st;
                    float2 n0 = cmadd(f01, A[i1], cmul(f00, A[i0]));
                    float2 n1 = cmadd(f11, A[i1], cmul(f10, A[i0]));
                    A[i0] = n0; A[i1] = n1;
                }
            }
        }
        // CNOT(0,1)
        {
#pragma unroll
            for (int j = 0; j < 8; j++) {
                float2 P = shflx(A[j], 2);
                if (l3 & 4) A[j] = P;
            }
        }
        // CNOT(2,3)
        if (l3 & 1) {
#pragma unroll
            for (int j = 0; j < 4; j++) { float2 t = A[j]; A[j] = A[j + 4]; A[j + 4] = t; }
        }
        // CNOT(4,5)
        { float2 t = A[2]; A[2] = A[3]; A[3] = t; }
        { float2 t = A[6]; A[6] = A[7]; A[7] = t; }
        // CNOT(1,2)
        {
#pragma unroll
            for (int j = 0; j < 8; j++) {
                float2 P = shflx(A[j], 1);
                if (l3 & 2) A[j] = P;
            }
        }
        // CNOT(3,4)
        { float2 t = A[4]; A[4] = A[6]; A[6] = t; }
        { float2 t = A[5]; A[5] = A[7]; A[7] = t; }
        // CNOT(5,0)
        {
            A[1] = shflx(A[1], 4);
            A[3] = shflx(A[3], 4);
            A[5] = shflx(A[5], 4);
            A[7] = shflx(A[7], 4);
        }
    }

    float p[8];
#pragma unroll
    for (int j = 0; j < 8; j++) p[j] = A[j].x * A[j].x + A[j].y * A[j].y;
    float sum = (p[0] + p[1]) + (p[2] + p[3]) + (p[4] + p[5]) + (p[6] + p[7]);
    float z[6];
    z[0] = (l3 & 4) ? -sum : sum;
    z[1] = (l3 & 2) ? -sum : sum;
    z[2] = (l3 & 1) ? -sum : sum;
    z[3] = sum - 2.f * ((p[4] + p[5]) + (p[6] + p[7]));
    z[4] = sum - 2.f * ((p[2] + p[3]) + (p[6] + p[7]));
    z[5] = sum - 2.f * ((p[1] + p[3]) + (p[5] + p[7]));
#pragma unroll
    for (int off = 4; off; off >>= 1) {
#pragma unroll
        for (int q = 0; q < 6; q++) z[q] += __shfl_xor_sync(0xffffffffu, z[q], off);
    }

    __half hv[16];
#pragma unroll
    for (int u = 0; u < 16; u++) {
        int j = l3 * 16 + u;
        float a = hb1[j];
#pragma unroll
        for (int i = 0; i < 6; i++) a += z[i] * hw1[i * 128 + j];
        hv[u] = __float2half_rn(fmaxf(a, 0.f));
    }
    uint4* dst = (uint4*)(g_af + (size_t)s * 128 + l3 * 16);
    dst[0] = *(uint4*)&hv[0];
    dst[1] = *(uint4*)&hv[8];
}

// ---------------- K3: HMMA fp16 GEMM  out = A[B,128] @ w2[128,1296] + b2 ----
#define K3_SMEM (32768 + 36864)

__global__ __launch_bounds__(256, 2)
void k3_mma(const float* __restrict__ b2, float* __restrict__ out, int B) {
    extern __shared__ char sm3[];
    __half* sA  = (__half*)sm3;            // 128 x 128
    __half* sBh = (__half*)(sm3 + 32768);  // 144 x 128

    int tid = threadIdx.x, lane = tid & 31, wid = tid >> 5;
    int n0 = blockIdx.x * 144;
    int m0 = blockIdx.y * 128;

    const uint4* gA = (const uint4*)g_af + (size_t)m0 * 16;
    uint4* dA = (uint4*)sA;
#pragma unroll
    for (int it = 0; it < 8; it++) {
        int i = it * 256 + tid;
        int r = i >> 4, c = i & 15;
        dA[r * 16 + (c ^ (r & 7))] = gA[i];
    }
    const uint4* gBh = (const uint4*)g_bh + (size_t)n0 * 16;
    uint4* dBh = (uint4*)sBh;
#pragma unroll
    for (int it = 0; it < 9; it++) {
        int i = it * 256 + tid;
        int r = i >> 4, c = i & 15;
        dBh[r * 16 + (c ^ (r & 7))] = gBh[i];
    }
    __syncthreads();

    uint32_t sAb = smem_u32(sA), sBhb = smem_u32(sBh);
    int la = lane & 7, hb = (lane >> 3) & 1, hc = lane >> 4;
    int arow = wid * 16 + la + (hb << 3);
    int brow = la + (hb << 3);

    float acc[18][4];
#pragma unroll
    for (int j = 0; j < 18; j++)
#pragma unroll
        for (int v = 0; v < 4; v++) acc[j][v] = 0.f;

#pragma unroll
    for (int ks = 0; ks < 8; ks++) {
        int ca = 2 * ks + hc;
        uint32_t a0, a1, a2, a3;
        ldsm4(a0, a1, a2, a3, smaddr(sAb, arow, ca));

#pragma unroll
        for (int p = 0; p < 9; p++) {
            uint32_t r0, r1, r2, r3;
            ldsm4(r0, r1, r2, r3, smaddr(sBhb, p * 16 + brow, ca));
            mma16816(acc[2 * p],     a0, a1, a2, a3, r0, r2);
            mma16816(acc[2 * p + 1], a0, a1, a2, a3, r1, r3);
        }
    }

    int orow0 = m0 + wid * 16 + (lane >> 2);
    float* op = out + (size_t)orow0 * 1296 + n0 + 2 * (lane & 3);
    const float* bp = b2 + n0 + 2 * (lane & 3);
#pragma unroll
    for (int j = 0; j < 18; j++) {
        float2 bias = *(const float2*)(bp + 8 * j);
        float2 v0 = make_float2(acc[j][0] + bias.x, acc[j][1] + bias.y);
        float2 v1 = make_float2(acc[j][2] + bias.x, acc[j][3] + bias.y);
        *(float2*)(op + 8 * j) = v0;
        *(float2*)(op + 8 * j + 8 * 1296) = v1;
    }
}

// ---------------- launch ----------------
extern "C" void kernel_launch(void* const* d_in, const int* in_sizes, int n_in,
                              void* d_out, int out_size) {
    const float* x   = (const float*)d_in[0];
    const float* ew1 = (const float*)d_in[1];
    const float* eb1 = (const float*)d_in[2];
    const float* ew2 = (const float*)d_in[3];
    const float* eb2 = (const float*)d_in[4];
    const float* qw  = (const float*)d_in[5];
    const float* hw1 = (const float*)d_in[6];
    const float* hb1 = (const float*)d_in[7];
    const float* hw2 = (const float*)d_in[8];
    const float* hb2 = (const float*)d_in[9];
    float* out = (float*)d_out;

    int B = in_sizes[0] / 512;

    cudaFuncSetAttribute(k3_mma, cudaFuncAttributeMaxDynamicSharedMemorySize, K3_SMEM);

    k0_rot<<<1, 32>>>(qw);
    k_w1pack<<<16, 256>>>(ew1);
    k_w2split<<<(1296 * 128 + 255) / 256, 256>>>(hw2);
    k1_encoder<<<B / 32, 256>>>(x, eb1, ew2, eb2, B);
    k2_circuit<<<(B * 8 + 255) / 256, 256>>>(hw1, hb1, B);
    dim3 g3(9, B / 128);
    k3_mma<<<g3, 256, K3_SMEM>>>(hb2, out, B);
}

// round 9
// speedup vs baseline: 3.1752x; 1.0049x over previous
#include <cuda_runtime.h>
#include <cuda_fp16.h>
#include <cstdint>

typedef unsigned long long ull;

#define BMAX 32768

// ---------------- scratch (static device globals: no allocation) ----------------
__device__ float g_angles[BMAX * 6];
__device__ __align__(16) float g_rot[18 * 8];
__device__ __align__(16) __half g_af[(size_t)BMAX * 128];  // A (activations) fp16
__device__ __align__(16) __half g_bh[1296 * 128];          // w2^T fp16 [N,K]
__device__ __align__(16) __half g_w1p[32 * 32 * 4 * 8];    // enc_w1 packed frags hi/lo

// ---------------- f32x2 packed helpers ----------------
__device__ __forceinline__ ull f2pack(float a, float b) {
    ull r;
    asm("mov.b64 %0, {%1, %2};" : "=l"(r) : "r"(__float_as_uint(a)), "r"(__float_as_uint(b)));
    return r;
}
__device__ __forceinline__ void f2unpack(ull v, float& a, float& b) {
    unsigned int lo, hi;
    asm("mov.b64 {%0, %1}, %2;" : "=r"(lo), "=r"(hi) : "l"(v));
    a = __uint_as_float(lo); b = __uint_as_float(hi);
}
__device__ __forceinline__ ull ffma2(ull a, ull b, ull c) {
    ull d;
    asm("fma.rn.f32x2 %0, %1, %2, %3;" : "=l"(d) : "l"(a), "l"(b), "l"(c));
    return d;
}
__device__ __forceinline__ ull fmul2(ull a, ull b) {
    ull d;
    asm("mul.rn.f32x2 %0, %1, %2;" : "=l"(d) : "l"(a), "l"(b));
    return d;
}

// ---------------- mma/ldmatrix helpers ----------------
__device__ __forceinline__ uint32_t smem_u32(const void* p) {
    uint32_t a;
    asm("{ .reg .u64 t; cvta.to.shared.u64 t, %1; cvt.u32.u64 %0, t; }" : "=r"(a) : "l"(p));
    return a;
}
__device__ __forceinline__ void ldsm4(uint32_t& r0, uint32_t& r1, uint32_t& r2, uint32_t& r3,
                                      uint32_t a) {
    asm volatile("ldmatrix.sync.aligned.m8n8.x4.shared.b16 {%0,%1,%2,%3}, [%4];"
                 : "=r"(r0), "=r"(r1), "=r"(r2), "=r"(r3) : "r"(a));
}
__device__ __forceinline__ void mma16816(float* d, uint32_t a0, uint32_t a1, uint32_t a2,
                                         uint32_t a3, uint32_t b0, uint32_t b1) {
    asm volatile(
        "mma.sync.aligned.m16n8k16.row.col.f32.f16.f16.f32 "
        "{%0,%1,%2,%3}, {%4,%5,%6,%7}, {%8,%9}, {%0,%1,%2,%3};"
        : "+f"(d[0]), "+f"(d[1]), "+f"(d[2]), "+f"(d[3])
        : "r"(a0), "r"(a1), "r"(a2), "r"(a3), "r"(b0), "r"(b1));
}
__device__ __forceinline__ uint32_t smaddr(uint32_t base, int row, int c) {
    return base + row * 256 + (((uint32_t)(c ^ (row & 7))) << 4);
}
__device__ __forceinline__ uint32_t h2pack(float a, float b) {
    __half2 h = __floats2half2_rn(a, b);
    return *(uint32_t*)&h;
}

// ---------------- K0: precompute Rot matrices ----------------
__global__ void k0_rot(const float* __restrict__ qw) {
    int t = threadIdx.x;
    if (t >= 18) return;
    float phi = qw[t * 3 + 0], th = qw[t * 3 + 1], om = qw[t * 3 + 2];
    float c = cosf(th * 0.5f), s = sinf(th * 0.5f);
    float ap = -(phi + om) * 0.5f, am = -(phi - om) * 0.5f;
    float sp, cp, sm, cm;
    sincosf(ap, &sp, &cp);
    sincosf(am, &sm, &cm);
    float* r = g_rot + t * 8;
    r[0] = cp * c;  r[1] = sp * c;
    r[2] = -cm * s; r[3] = sm * s;
    r[4] = cm * s;  r[5] = sm * s;
    r[6] = cp * c;  r[7] = -sp * c;
}

// ---------------- K0b: transpose head_w2 [128,1296] -> fp16 [1296,128] ----------------
__global__ void k_w2split(const float* __restrict__ w2) {
    int i = blockIdx.x * blockDim.x + threadIdx.x;
    if (i >= 1296 * 128) return;
    int n = i >> 7, k = i & 127;
    g_bh[i] = __float2half_rn(w2[k * 1296 + n]);
}

// ---------------- K0c: pack enc_w1 into mma-fragment order, fp16 hi/lo ----
__global__ void k_w1pack(const float* __restrict__ w1) {
    int i = blockIdx.x * blockDim.x + threadIdx.x;
    if (i >= 4096) return;
    int q = i & 3, ks = (i >> 2) & 31, n = i >> 7;
    int kc = ks * 16 + 4 * q;
    float v0 = w1[(kc + 0) * 32 + n];
    float v1 = w1[(kc + 1) * 32 + n];
    float v2 = w1[(kc + 2) * 32 + n];
    float v3 = w1[(kc + 3) * 32 + n];
    __half h[8];
    h[0] = __float2half_rn(v0); h[1] = __float2half_rn(v1);
    h[2] = __float2half_rn(v2); h[3] = __float2half_rn(v3);
    h[4] = __float2half_rn(v0 - __half2float(h[0]));
    h[5] = __float2half_rn(v1 - __half2float(h[1]));
    h[6] = __float2half_rn(v2 - __half2float(h[2]));
    h[7] = __float2half_rn(v3 - __half2float(h[3]));
    *(uint4*)(g_w1p + (size_t)i * 8) = *(uint4*)h;
}

// ---------------- K1: encoder via HMMA, 3-pass split, K-split x4 ------
__global__ __launch_bounds__(256)
void k1_encoder(const float* __restrict__ x,
                const float* __restrict__ b1,
                const float* __restrict__ w2,
                const float* __restrict__ b2, int base) {
    __shared__ float red[2][3][32][16];

    int tid = threadIdx.x, lane = tid & 31, wid = tid >> 5;
    int tile = wid >> 2, tw = wid & 3;
    int m0 = base + blockIdx.x * 32 + tile * 16;
    int g = lane >> 2, q = lane & 3;
    const float* xr0 = x + (size_t)(m0 + g) * 512;
    const float* xr1 = x + (size_t)(m0 + g + 8) * 512;

    float acc[4][4];
#pragma unroll
    for (int nf = 0; nf < 4; nf++)
#pragma unroll
        for (int v = 0; v < 4; v++) acc[nf][v] = 0.f;

#pragma unroll
    for (int kk = 0; kk < 8; kk++) {
        int ks = tw * 8 + kk;
        int kc = ks * 16 + 4 * q;
        float4 v0 = *(const float4*)(xr0 + kc);
        float4 v1 = *(const float4*)(xr1 + kc);

        uint32_t ah0 = h2pack(v0.x, v0.y), ah1 = h2pack(v1.x, v1.y);
        uint32_t ah2 = h2pack(v0.z, v0.w), ah3 = h2pack(v1.z, v1.w);
        __half2 t0 = *(__half2*)&ah0, t1 = *(__half2*)&ah1;
        __half2 t2 = *(__half2*)&ah2, t3 = *(__half2*)&ah3;
        uint32_t al0 = h2pack(v0.x - __low2float(t0), v0.y - __high2float(t0));
        uint32_t al1 = h2pack(v1.x - __low2float(t1), v1.y - __high2float(t1));
        uint32_t al2 = h2pack(v0.z - __low2float(t2), v0.w - __high2float(t2));
        uint32_t al3 = h2pack(v1.z - __low2float(t3), v1.w - __high2float(t3));

#pragma unroll
        for (int nf = 0; nf < 4; nf++) {
            int n = nf * 8 + g;
            uint4 bv = *(const uint4*)(g_w1p + (size_t)(((n * 32 + ks) * 4 + q)) * 8);
            mma16816(acc[nf], ah0, ah1, ah2, ah3, bv.x, bv.y);
            mma16816(acc[nf], ah0, ah1, ah2, ah3, bv.z, bv.w);
            mma16816(acc[nf], al0, al1, al2, al3, bv.x, bv.y);
        }
    }

    if (tw) {
        float4* dst = (float4*)red[tile][tw - 1][lane];
#pragma unroll
        for (int nf = 0; nf < 4; nf++) dst[nf] = *(float4*)acc[nf];
    }
    __syncthreads();
    if (tw != 0) return;

#pragma unroll
    for (int w = 0; w < 3; w++) {
        const float* src = red[tile][w][lane];
#pragma unroll
        for (int nf = 0; nf < 4; nf++)
#pragma unroll
            for (int v = 0; v < 4; v++) acc[nf][v] += src[nf * 4 + v];
    }

    float pr0[6], pr1[6];
#pragma unroll
    for (int i = 0; i < 6; i++) { pr0[i] = 0.f; pr1[i] = 0.f; }

#pragma unroll
    for (int nf = 0; nf < 4; nf++) {
        int c0 = nf * 8 + 2 * q;
        float bb0 = b1[c0], bb1 = b1[c0 + 1];
        float h00 = tanhf(acc[nf][0] + bb0);
        float h01 = tanhf(acc[nf][1] + bb1);
        float h10 = tanhf(acc[nf][2] + bb0);
        float h11 = tanhf(acc[nf][3] + bb1);
#pragma unroll
        for (int i = 0; i < 6; i++) {
            float w0 = w2[c0 * 6 + i], w1v = w2[(c0 + 1) * 6 + i];
            pr0[i] += h00 * w0 + h01 * w1v;
            pr1[i] += h10 * w0 + h11 * w1v;
        }
    }
#pragma unroll
    for (int m = 1; m <= 2; m <<= 1) {
#pragma unroll
        for (int i = 0; i < 6; i++) {
            pr0[i] += __shfl_xor_sync(0xffffffffu, pr0[i], m);
            pr1[i] += __shfl_xor_sync(0xffffffffu, pr1[i], m);
        }
    }
    if (q == 0) {
#pragma unroll
        for (int i = 0; i < 6; i++) {
            g_angles[(size_t)(m0 + g) * 6 + i] = pr0[i] + b2[i];
            g_angles[(size_t)(m0 + g + 8) * 6 + i] = pr1[i] + b2[i];
        }
    }
}

// ---------------- K2: quantum circuit — 4 samples/warp ----------------
__device__ __forceinline__ float2 shflx(float2 v, int m) {
    float2 r;
    r.x = __shfl_xor_sync(0xffffffffu, v.x, m);
    r.y = __shfl_xor_sync(0xffffffffu, v.y, m);
    return r;
}
__device__ __forceinline__ float2 cmul(float2 a, float2 b) {
    return make_float2(a.x * b.x - a.y * b.y, a.x * b.y + a.y * b.x);
}
__device__ __forceinline__ float2 cmadd(float2 a, float2 b, float2 acc) {
    return make_float2(acc.x + a.x * b.x - a.y * b.y, acc.y + a.x * b.y + a.y * b.x);
}

__global__ void k2_circuit(const float* __restrict__ hw1,
                           const float* __restrict__ hb1, int base) {
    int gt = blockIdx.x * blockDim.x + threadIdx.x;
    int warp = gt >> 5, lane = gt & 31;
    int l3 = lane & 7;
    int s = base + warp * 4 + (lane >> 3);

    float cs[6], sn[6];
#pragma unroll
    for (int q = 0; q < 6; q++) {
        float a = g_angles[s * 6 + q];
        __sincosf(0.5f * a, &sn[q], &cs[q]);
    }

    float2 A[8];
#pragma unroll
    for (int j = 0; j < 8; j++) A[j] = make_float2(0.f, 0.f);
    if (l3 == 0) A[0].x = 1.f;

#pragma unroll
    for (int L = 0; L < 3; L++) {
#pragma unroll
        for (int q = 0; q < 6; q++) {
            const ull* up = (const ull*)(g_rot + (L * 6 + q) * 8);
            ull u01 = up[0], u23 = up[1], u45 = up[2], u67 = up[3];
            float c = cs[q], s2 = sn[q];
            ull cp = f2pack(c, c), sp = f2pack(s2, s2), sn2 = f2pack(-s2, -s2);
            float2 f00, f01, f10, f11;
            f2unpack(ffma2(u23, sp, fmul2(u01, cp)), f00.x, f00.y);
            f2unpack(ffma2(u01, sn2, fmul2(u23, cp)), f01.x, f01.y);
            f2unpack(ffma2(u67, sp, fmul2(u45, cp)), f10.x, f10.y);
            f2unpack(ffma2(u45, sn2, fmul2(u67, cp)), f11.x, f11.y);

            if (q <= 2) {
                int m = 4 >> q;
                bool hi = (l3 & m) != 0;
                float2 ua = hi ? f11 : f00;
                float2 ub = hi ? f10 : f01;
#pragma unroll
                for (int j = 0; j < 8; j++) {
                    float2 P = shflx(A[j], m);
                    A[j] = cmadd(ub, P, cmul(ua, A[j]));
                }
            } else {
                int lb = 5 - q;
                int st = 1 << lb;
#pragma unroll
                for (int i0 = 0; i0 < 8; i0++) {
                    if (i0 & st) continue;
                    int i1 = i0 | st;
                    float2 n0 = cmadd(f01, A[i1], cmul(f00, A[i0]));
                    float2 n1 = cmadd(f11, A[i1], cmul(f10, A[i0]));
                    A[i0] = n0; A[i1] = n1;
                }
            }
        }
        // CNOT ladder
        {
#pragma unroll
            for (int j = 0; j < 8; j++) {
                float2 P = shflx(A[j], 2);
                if (l3 & 4) A[j] = P;
            }
        }
        if (l3 & 1) {
#pragma unroll
            for (int j = 0; j < 4; j++) { float2 t = A[j]; A[j] = A[j + 4]; A[j + 4] = t; }
        }
        { float2 t = A[2]; A[2] = A[3]; A[3] = t; }
        { float2 t = A[6]; A[6] = A[7]; A[7] = t; }
        {
#pragma unroll
            for (int j = 0; j < 8; j++) {
                float2 P = shflx(A[j], 1);
                if (l3 & 2) A[j] = P;
            }
        }
        { float2 t = A[4]; A[4] = A[6]; A[6] = t; }
        { float2 t = A[5]; A[5] = A[7]; A[7] = t; }
        {
            A[1] = shflx(A[1], 4);
            A[3] = shflx(A[3], 4);
            A[5] = shflx(A[5], 4);
            A[7] = shflx(A[7], 4);
        }
    }

    float p[8];
#pragma unroll
    for (int j = 0; j < 8; j++) p[j] = A[j].x * A[j].x + A[j].y * A[j].y;
    float sum = (p[0] + p[1]) + (p[2] + p[3]) + (p[4] + p[5]) + (p[6] + p[7]);
    float z[6];
    z[0] = (l3 & 4) ? -sum : sum;
    z[1] = (l3 & 2) ? -sum : sum;
    z[2] = (l3 & 1) ? -sum : sum;
    z[3] = sum - 2.f * ((p[4] + p[5]) + (p[6] + p[7]));
    z[4] = sum - 2.f * ((p[2] + p[3]) + (p[6] + p[7]));
    z[5] = sum - 2.f * ((p[1] + p[3]) + (p[5] + p[7]));
#pragma unroll
    for (int off = 4; off; off >>= 1) {
#pragma unroll
        for (int q = 0; q < 6; q++) z[q] += __shfl_xor_sync(0xffffffffu, z[q], off);
    }

    __half hv[16];
#pragma unroll
    for (int u = 0; u < 16; u++) {
        int j = l3 * 16 + u;
        float a = hb1[j];
#pragma unroll
        for (int i = 0; i < 6; i++) a += z[i] * hw1[i * 128 + j];
        hv[u] = __float2half_rn(fmaxf(a, 0.f));
    }
    uint4* dst = (uint4*)(g_af + (size_t)s * 128 + l3 * 16);
    dst[0] = *(uint4*)&hv[0];
    dst[1] = *(uint4*)&hv[8];
}

// ---------------- K3: HMMA fp16 GEMM  out = A[B,128] @ w2[128,1296] + b2 ----
#define K3_SMEM (32768 + 36864)

__global__ __launch_bounds__(256, 2)
void k3_mma(const float* __restrict__ b2, float* __restrict__ out, int base) {
    extern __shared__ char sm3[];
    __half* sA  = (__half*)sm3;            // 128 x 128
    __half* sBh = (__half*)(sm3 + 32768);  // 144 x 128

    int tid = threadIdx.x, lane = tid & 31, wid = tid >> 5;
    int n0 = blockIdx.x * 144;
    int m0 = base + blockIdx.y * 128;

    const uint4* gA = (const uint4*)g_af + (size_t)m0 * 16;
    uint4* dA = (uint4*)sA;
#pragma unroll
    for (int it = 0; it < 8; it++) {
        int i = it * 256 + tid;
        int r = i >> 4, c = i & 15;
        dA[r * 16 + (c ^ (r & 7))] = gA[i];
    }
    const uint4* gBh = (const uint4*)g_bh + (size_t)n0 * 16;
    uint4* dBh = (uint4*)sBh;
#pragma unroll
    for (int it = 0; it < 9; it++) {
        int i = it * 256 + tid;
        int r = i >> 4, c = i & 15;
        dBh[r * 16 + (c ^ (r & 7))] = gBh[i];
    }
    __syncthreads();

    uint32_t sAb = smem_u32(sA), sBhb = smem_u32(sBh);
    int la = lane & 7, hb = (lane >> 3) & 1, hc = lane >> 4;
    int arow = wid * 16 + la + (hb << 3);
    int brow = la + (hb << 3);

    float acc[18][4];
#pragma unroll
    for (int j = 0; j < 18; j++)
#pragma unroll
        for (int v = 0; v < 4; v++) acc[j][v] = 0.f;

#pragma unroll
    for (int ks = 0; ks < 8; ks++) {
        int ca = 2 * ks + hc;
        uint32_t a0, a1, a2, a3;
        ldsm4(a0, a1, a2, a3, smaddr(sAb, arow, ca));

#pragma unroll
        for (int p = 0; p < 9; p++) {
            uint32_t r0, r1, r2, r3;
            ldsm4(r0, r1, r2, r3, smaddr(sBhb, p * 16 + brow, ca));
            mma16816(acc[2 * p],     a0, a1, a2, a3, r0, r2);
            mma16816(acc[2 * p + 1], a0, a1, a2, a3, r1, r3);
        }
    }

    int orow0 = m0 + wid * 16 + (lane >> 2);
    float* op = out + (size_t)orow0 * 1296 + n0 + 2 * (lane & 3);
    const float* bp = b2 + n0 + 2 * (lane & 3);
#pragma unroll
    for (int j = 0; j < 18; j++) {
        float2 bias = *(const float2*)(bp + 8 * j);
        float2 v0 = make_float2(acc[j][0] + bias.x, acc[j][1] + bias.y);
        float2 v1 = make_float2(acc[j][2] + bias.x, acc[j][3] + bias.y);
        *(float2*)(op + 8 * j) = v0;
        *(float2*)(op + 8 * j + 8 * 1296) = v1;
    }
}

// ---------------- launch: 2-stream x 4-chunk pipeline ----------------
extern "C" void kernel_launch(void* const* d_in, const int* in_sizes, int n_in,
                              void* d_out, int out_size) {
    const float* x   = (const float*)d_in[0];
    const float* ew1 = (const float*)d_in[1];
    const float* eb1 = (const float*)d_in[2];
    const float* ew2 = (const float*)d_in[3];
    const float* eb2 = (const float*)d_in[4];
    const float* qw  = (const float*)d_in[5];
    const float* hw1 = (const float*)d_in[6];
    const float* hb1 = (const float*)d_in[7];
    const float* hw2 = (const float*)d_in[8];
    const float* hb2 = (const float*)d_in[9];
    float* out = (float*)d_out;

    int B = in_sizes[0] / 512;

    static bool inited = false;
    static cudaStream_t st[2];
    static cudaEvent_t evFork, evJoin0, evJoin1;
    if (!inited) {
        cudaStreamCreateWithFlags(&st[0], cudaStreamNonBlocking);
        cudaStreamCreateWithFlags(&st[1], cudaStreamNonBlocking);
        cudaEventCreateWithFlags(&evFork, cudaEventDisableTiming);
        cudaEventCreateWithFlags(&evJoin0, cudaEventDisableTiming);
        cudaEventCreateWithFlags(&evJoin1, cudaEventDisableTiming);
        cudaFuncSetAttribute(k3_mma, cudaFuncAttributeMaxDynamicSharedMemorySize, K3_SMEM);
        inited = true;
    }

    // prep (batch-invariant) on the capture (default) stream
    k0_rot<<<1, 32>>>(qw);
    k_w1pack<<<16, 256>>>(ew1);
    k_w2split<<<(1296 * 128 + 255) / 256, 256>>>(hw2);

    // fork
    cudaEventRecord(evFork, 0);
    cudaStreamWaitEvent(st[0], evFork, 0);
    cudaStreamWaitEvent(st[1], evFork, 0);

    const int NCH = 4;
    int chunk = B / NCH;  // 8192 (divisible by 512)
    for (int c = 0; c < NCH; c++) {
        cudaStream_t s = st[c & 1];
        int base = c * chunk;
        k1_encoder<<<chunk / 32, 256, 0, s>>>(x, eb1, ew2, eb2, base);
        k2_circuit<<<(chunk * 8) / 256, 256, 0, s>>>(hw1, hb1, base);
        dim3 g3(9, chunk / 128);
        k3_mma<<<g3, 256, K3_SMEM, s>>>(hb2, out, base);
    }

    // join
    cudaEventRecord(evJoin0, st[0]);
    cudaEventRecord(evJoin1, st[1]);
    cudaStreamWaitEvent(0, evJoin0, 0);
    cudaStreamWaitEvent(0, evJoin1, 0);
}

// round 10
// speedup vs baseline: 3.4425x; 1.0842x over previous
#include <cuda_runtime.h>
#include <cuda_fp16.h>
#include <cstdint>

typedef unsigned long long ull;

#define BMAX 32768

// ---------------- scratch (static device globals: no allocation) ----------------
__device__ __align__(16) float g_rot[18 * 8];
__device__ __align__(16) __half g_af[(size_t)BMAX * 128];  // A (activations) fp16
__device__ __align__(16) __half g_bh[1296 * 128];          // w2^T fp16 [N,K]
__device__ __align__(16) __half g_w1p[32 * 32 * 4 * 8];    // enc_w1 packed frags hi/lo

// ---------------- f32x2 packed helpers ----------------
__device__ __forceinline__ ull f2pack(float a, float b) {
    ull r;
    asm("mov.b64 %0, {%1, %2};" : "=l"(r) : "r"(__float_as_uint(a)), "r"(__float_as_uint(b)));
    return r;
}
__device__ __forceinline__ void f2unpack(ull v, float& a, float& b) {
    unsigned int lo, hi;
    asm("mov.b64 {%0, %1}, %2;" : "=r"(lo), "=r"(hi) : "l"(v));
    a = __uint_as_float(lo); b = __uint_as_float(hi);
}
__device__ __forceinline__ ull ffma2(ull a, ull b, ull c) {
    ull d;
    asm("fma.rn.f32x2 %0, %1, %2, %3;" : "=l"(d) : "l"(a), "l"(b), "l"(c));
    return d;
}
__device__ __forceinline__ ull fmul2(ull a, ull b) {
    ull d;
    asm("mul.rn.f32x2 %0, %1, %2;" : "=l"(d) : "l"(a), "l"(b));
    return d;
}

// ---------------- mma/ldmatrix helpers ----------------
__device__ __forceinline__ uint32_t smem_u32(const void* p) {
    uint32_t a;
    asm("{ .reg .u64 t; cvta.to.shared.u64 t, %1; cvt.u32.u64 %0, t; }" : "=r"(a) : "l"(p));
    return a;
}
__device__ __forceinline__ void ldsm4(uint32_t& r0, uint32_t& r1, uint32_t& r2, uint32_t& r3,
                                      uint32_t a) {
    asm volatile("ldmatrix.sync.aligned.m8n8.x4.shared.b16 {%0,%1,%2,%3}, [%4];"
                 : "=r"(r0), "=r"(r1), "=r"(r2), "=r"(r3) : "r"(a));
}
__device__ __forceinline__ void mma16816(float* d, uint32_t a0, uint32_t a1, uint32_t a2,
                                         uint32_t a3, uint32_t b0, uint32_t b1) {
    asm volatile(
        "mma.sync.aligned.m16n8k16.row.col.f32.f16.f16.f32 "
        "{%0,%1,%2,%3}, {%4,%5,%6,%7}, {%8,%9}, {%0,%1,%2,%3};"
        : "+f"(d[0]), "+f"(d[1]), "+f"(d[2]), "+f"(d[3])
        : "r"(a0), "r"(a1), "r"(a2), "r"(a3), "r"(b0), "r"(b1));
}
__device__ __forceinline__ uint32_t smaddr(uint32_t base, int row, int c) {
    return base + row * 256 + (((uint32_t)(c ^ (row & 7))) << 4);
}
__device__ __forceinline__ uint32_t h2pack(float a, float b) {
    __half2 h = __floats2half2_rn(a, b);
    return *(uint32_t*)&h;
}

// ---------------- K0: precompute Rot matrices ----------------
__global__ void k0_rot(const float* __restrict__ qw) {
    int t = threadIdx.x;
    if (t >= 18) return;
    float phi = qw[t * 3 + 0], th = qw[t * 3 + 1], om = qw[t * 3 + 2];
    float c = cosf(th * 0.5f), s = sinf(th * 0.5f);
    float ap = -(phi + om) * 0.5f, am = -(phi - om) * 0.5f;
    float sp, cp, sm, cm;
    sincosf(ap, &sp, &cp);
    sincosf(am, &sm, &cm);
    float* r = g_rot + t * 8;
    r[0] = cp * c;  r[1] = sp * c;
    r[2] = -cm * s; r[3] = sm * s;
    r[4] = cm * s;  r[5] = sm * s;
    r[6] = cp * c;  r[7] = -sp * c;
}

// ---------------- K0b: transpose head_w2 [128,1296] -> fp16 [1296,128] ----------------
__global__ void k_w2split(const float* __restrict__ w2) {
    int i = blockIdx.x * blockDim.x + threadIdx.x;
    if (i >= 1296 * 128) return;
    int n = i >> 7, k = i & 127;
    g_bh[i] = __float2half_rn(w2[k * 1296 + n]);
}

// ---------------- K0c: pack enc_w1 into mma-fragment order, fp16 hi/lo ----
__global__ void k_w1pack(const float* __restrict__ w1) {
    int i = blockIdx.x * blockDim.x + threadIdx.x;
    if (i >= 4096) return;
    int q = i & 3, ks = (i >> 2) & 31, n = i >> 7;
    int kc = ks * 16 + 4 * q;
    float v0 = w1[(kc + 0) * 32 + n];
    float v1 = w1[(kc + 1) * 32 + n];
    float v2 = w1[(kc + 2) * 32 + n];
    float v3 = w1[(kc + 3) * 32 + n];
    __half h[8];
    h[0] = __float2half_rn(v0); h[1] = __float2half_rn(v1);
    h[2] = __float2half_rn(v2); h[3] = __float2half_rn(v3);
    h[4] = __float2half_rn(v0 - __half2float(h[0]));
    h[5] = __float2half_rn(v1 - __half2float(h[1]));
    h[6] = __float2half_rn(v2 - __half2float(h[2]));
    h[7] = __float2half_rn(v3 - __half2float(h[3]));
    *(uint4*)(g_w1p + (size_t)i * 8) = *(uint4*)h;
}

// ---------------- circuit helpers ----------------
__device__ __forceinline__ float2 shflx(float2 v, int m) {
    float2 r;
    r.x = __shfl_xor_sync(0xffffffffu, v.x, m);
    r.y = __shfl_xor_sync(0xffffffffu, v.y, m);
    return r;
}
__device__ __forceinline__ float2 cmul(float2 a, float2 b) {
    return make_float2(a.x * b.x - a.y * b.y, a.x * b.y + a.y * b.x);
}
__device__ __forceinline__ float2 cmadd(float2 a, float2 b, float2 acc) {
    return make_float2(acc.x + a.x * b.x - a.y * b.y, acc.y + a.x * b.y + a.y * b.x);
}

// ---------------- K12: fused encoder (HMMA) + circuit, 32 samples/CTA ----------------
__global__ __launch_bounds__(256)
void k12_fused(const float* __restrict__ x,
               const float* __restrict__ b1,
               const float* __restrict__ w2,
               const float* __restrict__ b2,
               const float* __restrict__ hw1,
               const float* __restrict__ hb1, int base) {
    __shared__ float red[2][3][32][16];
    __shared__ float sang[32][6];

    int tid = threadIdx.x, lane = tid & 31, wid = tid >> 5;

    // ======== phase 1: encoder ========
    {
        int tile = wid >> 2, tw = wid & 3;
        int m0 = base + blockIdx.x * 32 + tile * 16;
        int g = lane >> 2, q = lane & 3;
        const float* xr0 = x + (size_t)(m0 + g) * 512;
        const float* xr1 = x + (size_t)(m0 + g + 8) * 512;

        float acc[4][4];
#pragma unroll
        for (int nf = 0; nf < 4; nf++)
#pragma unroll
            for (int v = 0; v < 4; v++) acc[nf][v] = 0.f;

#pragma unroll
        for (int kk = 0; kk < 8; kk++) {
            int ks = tw * 8 + kk;
            int kc = ks * 16 + 4 * q;
            float4 v0 = *(const float4*)(xr0 + kc);
            float4 v1 = *(const float4*)(xr1 + kc);

            uint32_t ah0 = h2pack(v0.x, v0.y), ah1 = h2pack(v1.x, v1.y);
            uint32_t ah2 = h2pack(v0.z, v0.w), ah3 = h2pack(v1.z, v1.w);
            __half2 t0 = *(__half2*)&ah0, t1 = *(__half2*)&ah1;
            __half2 t2 = *(__half2*)&ah2, t3 = *(__half2*)&ah3;
            uint32_t al0 = h2pack(v0.x - __low2float(t0), v0.y - __high2float(t0));
            uint32_t al1 = h2pack(v1.x - __low2float(t1), v1.y - __high2float(t1));
            uint32_t al2 = h2pack(v0.z - __low2float(t2), v0.w - __high2float(t2));
            uint32_t al3 = h2pack(v1.z - __low2float(t3), v1.w - __high2float(t3));

#pragma unroll
            for (int nf = 0; nf < 4; nf++) {
                int n = nf * 8 + g;
                uint4 bv = *(const uint4*)(g_w1p + (size_t)(((n * 32 + ks) * 4 + q)) * 8);
                mma16816(acc[nf], ah0, ah1, ah2, ah3, bv.x, bv.y);
                mma16816(acc[nf], ah0, ah1, ah2, ah3, bv.z, bv.w);
                mma16816(acc[nf], al0, al1, al2, al3, bv.x, bv.y);
            }
        }

        if (tw) {
            float4* dst = (float4*)red[tile][tw - 1][lane];
#pragma unroll
            for (int nf = 0; nf < 4; nf++) dst[nf] = *(float4*)acc[nf];
        }
        __syncthreads();

        if (tw == 0) {
#pragma unroll
            for (int w = 0; w < 3; w++) {
                const float* src = red[tile][w][lane];
#pragma unroll
                for (int nf = 0; nf < 4; nf++)
#pragma unroll
                    for (int v = 0; v < 4; v++) acc[nf][v] += src[nf * 4 + v];
            }

            float pr0[6], pr1[6];
#pragma unroll
            for (int i = 0; i < 6; i++) { pr0[i] = 0.f; pr1[i] = 0.f; }

#pragma unroll
            for (int nf = 0; nf < 4; nf++) {
                int c0 = nf * 8 + 2 * q;
                float bb0 = b1[c0], bb1 = b1[c0 + 1];
                float h00 = tanhf(acc[nf][0] + bb0);
                float h01 = tanhf(acc[nf][1] + bb1);
                float h10 = tanhf(acc[nf][2] + bb0);
                float h11 = tanhf(acc[nf][3] + bb1);
#pragma unroll
                for (int i = 0; i < 6; i++) {
                    float w0 = w2[c0 * 6 + i], w1v = w2[(c0 + 1) * 6 + i];
                    pr0[i] += h00 * w0 + h01 * w1v;
                    pr1[i] += h10 * w0 + h11 * w1v;
                }
            }
#pragma unroll
            for (int m = 1; m <= 2; m <<= 1) {
#pragma unroll
                for (int i = 0; i < 6; i++) {
                    pr0[i] += __shfl_xor_sync(0xffffffffu, pr0[i], m);
                    pr1[i] += __shfl_xor_sync(0xffffffffu, pr1[i], m);
                }
            }
            if (q == 0) {
#pragma unroll
                for (int i = 0; i < 6; i++) {
                    sang[tile * 16 + g][i] = pr0[i] + b2[i];
                    sang[tile * 16 + g + 8][i] = pr1[i] + b2[i];
                }
            }
        }
    }
    __syncthreads();

    // ======== phase 2: circuit (4 samples/warp, 8 lanes/sample) ========
    int l3 = lane & 7;
    int ls = wid * 4 + (lane >> 3);
    int s = base + blockIdx.x * 32 + ls;

    float cs[6], sn[6];
#pragma unroll
    for (int q = 0; q < 6; q++) {
        float a = sang[ls][q];
        __sincosf(0.5f * a, &sn[q], &cs[q]);
    }

    float2 A[8];
#pragma unroll
    for (int j = 0; j < 8; j++) A[j] = make_float2(0.f, 0.f);
    if (l3 == 0) A[0].x = 1.f;

#pragma unroll
    for (int L = 0; L < 3; L++) {
#pragma unroll
        for (int q = 0; q < 6; q++) {
            const ull* up = (const ull*)(g_rot + (L * 6 + q) * 8);
            ull u01 = up[0], u23 = up[1], u45 = up[2], u67 = up[3];
            float c = cs[q], s2 = sn[q];
            ull cp = f2pack(c, c), sp = f2pack(s2, s2), sn2 = f2pack(-s2, -s2);
            float2 f00, f01, f10, f11;
            f2unpack(ffma2(u23, sp, fmul2(u01, cp)), f00.x, f00.y);
            f2unpack(ffma2(u01, sn2, fmul2(u23, cp)), f01.x, f01.y);
            f2unpack(ffma2(u67, sp, fmul2(u45, cp)), f10.x, f10.y);
            f2unpack(ffma2(u45, sn2, fmul2(u67, cp)), f11.x, f11.y);

            if (q <= 2) {
                int m = 4 >> q;
                bool hi = (l3 & m) != 0;
                float2 ua = hi ? f11 : f00;
                float2 ub = hi ? f10 : f01;
#pragma unroll
                for (int j = 0; j < 8; j++) {
                    float2 P = shflx(A[j], m);
                    A[j] = cmadd(ub, P, cmul(ua, A[j]));
                }
            } else {
                int lb = 5 - q;
                int st = 1 << lb;
#pragma unroll
                for (int i0 = 0; i0 < 8; i0++) {
                    if (i0 & st) continue;
                    int i1 = i0 | st;
                    float2 n0 = cmadd(f01, A[i1], cmul(f00, A[i0]));
                    float2 n1 = cmadd(f11, A[i1], cmul(f10, A[i0]));
                    A[i0] = n0; A[i1] = n1;
                }
            }
        }
        // CNOT ladder
        {
#pragma unroll
            for (int j = 0; j < 8; j++) {
                float2 P = shflx(A[j], 2);
                if (l3 & 4) A[j] = P;
            }
        }
        if (l3 & 1) {
#pragma unroll
            for (int j = 0; j < 4; j++) { float2 t = A[j]; A[j] = A[j + 4]; A[j + 4] = t; }
        }
        { float2 t = A[2]; A[2] = A[3]; A[3] = t; }
        { float2 t = A[6]; A[6] = A[7]; A[7] = t; }
        {
#pragma unroll
            for (int j = 0; j < 8; j++) {
                float2 P = shflx(A[j], 1);
                if (l3 & 2) A[j] = P;
            }
        }
        { float2 t = A[4]; A[4] = A[6]; A[6] = t; }
        { float2 t = A[5]; A[5] = A[7]; A[7] = t; }
        {
            A[1] = shflx(A[1], 4);
            A[3] = shflx(A[3], 4);
            A[5] = shflx(A[5], 4);
            A[7] = shflx(A[7], 4);
        }
    }

    float p[8];
#pragma unroll
    for (int j = 0; j < 8; j++) p[j] = A[j].x * A[j].x + A[j].y * A[j].y;
    float sum = (p[0] + p[1]) + (p[2] + p[3]) + (p[4] + p[5]) + (p[6] + p[7]);
    float z[6];
    z[0] = (l3 & 4) ? -sum : sum;
    z[1] = (l3 & 2) ? -sum : sum;
    z[2] = (l3 & 1) ? -sum : sum;
    z[3] = sum - 2.f * ((p[4] + p[5]) + (p[6] + p[7]));
    z[4] = sum - 2.f * ((p[2] + p[3]) + (p[6] + p[7]));
    z[5] = sum - 2.f * ((p[1] + p[3]) + (p[5] + p[7]));
#pragma unroll
    for (int off = 4; off; off >>= 1) {
#pragma unroll
        for (int q = 0; q < 6; q++) z[q] += __shfl_xor_sync(0xffffffffu, z[q], off);
    }

    __half hv[16];
#pragma unroll
    for (int u = 0; u < 16; u++) {
        int j = l3 * 16 + u;
        float a = hb1[j];
#pragma unroll
        for (int i = 0; i < 6; i++) a += z[i] * hw1[i * 128 + j];
        hv[u] = __float2half_rn(fmaxf(a, 0.f));
    }
    uint4* dst = (uint4*)(g_af + (size_t)s * 128 + l3 * 16);
    dst[0] = *(uint4*)&hv[0];
    dst[1] = *(uint4*)&hv[8];
}

// ---------------- K3: HMMA fp16 GEMM  out = A[B,128] @ w2[128,1296] + b2 ----
#define K3_SMEM (32768 + 36864)

__global__ __launch_bounds__(256, 2)
void k3_mma(const float* __restrict__ b2, float* __restrict__ out, int base) {
    extern __shared__ char sm3[];
    __half* sA  = (__half*)sm3;            // 128 x 128
    __half* sBh = (__half*)(sm3 + 32768);  // 144 x 128

    int tid = threadIdx.x, lane = tid & 31, wid = tid >> 5;
    int n0 = blockIdx.x * 144;
    int m0 = base + blockIdx.y * 128;

    const uint4* gA = (const uint4*)g_af + (size_t)m0 * 16;
    uint4* dA = (uint4*)sA;
#pragma unroll
    for (int it = 0; it < 8; it++) {
        int i = it * 256 + tid;
        int r = i >> 4, c = i & 15;
        dA[r * 16 + (c ^ (r & 7))] = gA[i];
    }
    const uint4* gBh = (const uint4*)g_bh + (size_t)n0 * 16;
    uint4* dBh = (uint4*)sBh;
#pragma unroll
    for (int it = 0; it < 9; it++) {
        int i = it * 256 + tid;
        int r = i >> 4, c = i & 15;
        dBh[r * 16 + (c ^ (r & 7))] = gBh[i];
    }
    __syncthreads();

    uint32_t sAb = smem_u32(sA), sBhb = smem_u32(sBh);
    int la = lane & 7, hb = (lane >> 3) & 1, hc = lane >> 4;
    int arow = wid * 16 + la + (hb << 3);
    int brow = la + (hb << 3);

    float acc[18][4];
#pragma unroll
    for (int j = 0; j < 18; j++)
#pragma unroll
        for (int v = 0; v < 4; v++) acc[j][v] = 0.f;

#pragma unroll
    for (int ks = 0; ks < 8; ks++) {
        int ca = 2 * ks + hc;
        uint32_t a0, a1, a2, a3;
        ldsm4(a0, a1, a2, a3, smaddr(sAb, arow, ca));

#pragma unroll
        for (int p = 0; p < 9; p++) {
            uint32_t r0, r1, r2, r3;
            ldsm4(r0, r1, r2, r3, smaddr(sBhb, p * 16 + brow, ca));
            mma16816(acc[2 * p],     a0, a1, a2, a3, r0, r2);
            mma16816(acc[2 * p + 1], a0, a1, a2, a3, r1, r3);
        }
    }

    int orow0 = m0 + wid * 16 + (lane >> 2);
    float* op = out + (size_t)orow0 * 1296 + n0 + 2 * (lane & 3);
    const float* bp = b2 + n0 + 2 * (lane & 3);
#pragma unroll
    for (int j = 0; j < 18; j++) {
        float2 bias = *(const float2*)(bp + 8 * j);
        float2 v0 = make_float2(acc[j][0] + bias.x, acc[j][1] + bias.y);
        float2 v1 = make_float2(acc[j][2] + bias.x, acc[j][3] + bias.y);
        *(float2*)(op + 8 * j) = v0;
        *(float2*)(op + 8 * j + 8 * 1296) = v1;
    }
}

// ---------------- launch: fused k12 + 2-chunk 2-stream pipeline ----------------
extern "C" void kernel_launch(void* const* d_in, const int* in_sizes, int n_in,
                              void* d_out, int out_size) {
    const float* x   = (const float*)d_in[0];
    const float* ew1 = (const float*)d_in[1];
    const float* eb1 = (const float*)d_in[2];
    const float* ew2 = (const float*)d_in[3];
    const float* eb2 = (const float*)d_in[4];
    const float* qw  = (const float*)d_in[5];
    const float* hw1 = (const float*)d_in[6];
    const float* hb1 = (const float*)d_in[7];
    const float* hw2 = (const float*)d_in[8];
    const float* hb2 = (const float*)d_in[9];
    float* out = (float*)d_out;

    int B = in_sizes[0] / 512;

    static bool inited = false;
    static cudaStream_t st[2];
    static cudaEvent_t evFork, evJoin0, evJoin1;
    if (!inited) {
        cudaStreamCreateWithFlags(&st[0], cudaStreamNonBlocking);
        cudaStreamCreateWithFlags(&st[1], cudaStreamNonBlocking);
        cudaEventCreateWithFlags(&evFork, cudaEventDisableTiming);
        cudaEventCreateWithFlags(&evJoin0, cudaEventDisableTiming);
        cudaEventCreateWithFlags(&evJoin1, cudaEventDisableTiming);
        cudaFuncSetAttribute(k3_mma, cudaFuncAttributeMaxDynamicSharedMemorySize, K3_SMEM);
        inited = true;
    }

    // prep (batch-invariant) on the capture (default) stream
    k0_rot<<<1, 32>>>(qw);
    k_w1pack<<<16, 256>>>(ew1);
    k_w2split<<<(1296 * 128 + 255) / 256, 256>>>(hw2);

    // fork
    cudaEventRecord(evFork, 0);
    cudaStreamWaitEvent(st[0], evFork, 0);
    cudaStreamWaitEvent(st[1], evFork, 0);

    const int NCH = 2;
    int chunk = B / NCH;  // 16384
    for (int c = 0; c < NCH; c++) {
        cudaStream_t s = st[c];
        int base = c * chunk;
        k12_fused<<<chunk / 32, 256, 0, s>>>(x, eb1, ew2, eb2, hw1, hb1, base);
        dim3 g3(9, chunk / 128);
        k3_mma<<<g3, 256, K3_SMEM, s>>>(hb2, out, base);
    }

    // join
    cudaEventRecord(evJoin0, st[0]);
    cudaEventRecord(evJoin1, st[1]);
    cudaStreamWaitEvent(0, evJoin0, 0);
    cudaStreamWaitEvent(0, evJoin1, 0);
}